// round 2
// baseline (speedup 1.0000x reference)
#include <cuda_runtime.h>
#include <math.h>

// Problem shape constants
#define Bn   16
#define Sn   1024
#define CIN  1280
#define Dn   512
#define Hn   8
#define HDn  64
#define TOK  (Bn*Sn)   // 16384

// ---------------------------------------------------------------------------
// Static scratch (no cudaMalloc allowed)
// ---------------------------------------------------------------------------
__device__ float g_h   [TOK * Dn];        //  33.5 MB  h = x@w_in + b_in
__device__ float g_qkv [TOK * 3 * Dn];    // 100.7 MB  qkv (rope applied in place)
__device__ float g_attn[TOK * Dn];        //  33.5 MB  attention out (B,S,H,HD)
__device__ float g_oprj[TOK * Dn];        //  33.5 MB  o @ w_out
__device__ float g_h2  [TOK * Dn];        //  33.5 MB  ln1 output
__device__ float g_f1  [TOK * 4 * Dn];    // 134.2 MB  relu(ffn1)
__device__ float g_f2  [TOK * Dn];        //  33.5 MB  ffn2
__device__ float g_sin [Sn * 32];
__device__ float g_cos [Sn * 32];

// ---------------------------------------------------------------------------
// SGEMM: C[M,N] = A[M,K] @ B[K,N] + bias (optional ReLU)
// 128x128 block tile, BK=16, 256 threads, 8x8 per-thread register tile.
// Requires: M%128==0, N%128==0, K%16==0 (all shapes satisfy).
// ---------------------------------------------------------------------------
__global__ void __launch_bounds__(256, 2)
sgemm_bias(const float* __restrict__ A, const float* __restrict__ Bm,
           const float* __restrict__ bias, float* __restrict__ C,
           int M, int N, int K, int relu)
{
    __shared__ float As[16][128];
    __shared__ float Bs[16][128];

    const int t  = threadIdx.x;
    const int tr = t >> 4;          // 0..15 (row group)
    const int tc = t & 15;          // 0..15 (col group)
    const int bx = blockIdx.x;      // N tile
    const int by = blockIdx.y;      // M tile

    const float* Ab = A  + (size_t)by * 128 * K;
    const float* Bb = Bm + (size_t)bx * 128;

    float acc[8][8];
#pragma unroll
    for (int i = 0; i < 8; i++)
#pragma unroll
        for (int j = 0; j < 8; j++) acc[i][j] = 0.f;

    for (int k0 = 0; k0 < K; k0 += 16) {
#pragma unroll
        for (int u = 0; u < 2; u++) {
            int idx  = t + u * 256;                  // 512 float4 per tile
            // A tile: 128 rows x 4 float4 (16 k), store transposed As[k][m]
            int arow = idx >> 2, ac4 = (idx & 3) << 2;
            float4 av = *(const float4*)(Ab + (size_t)arow * K + k0 + ac4);
            As[ac4 + 0][arow] = av.x;
            As[ac4 + 1][arow] = av.y;
            As[ac4 + 2][arow] = av.z;
            As[ac4 + 3][arow] = av.w;
            // B tile: 16 rows x 32 float4
            int brow = idx >> 5, bc = (idx & 31) << 2;
            float4 bv = *(const float4*)(Bb + (size_t)(k0 + brow) * N + bc);
            *(float4*)&Bs[brow][bc] = bv;
        }
        __syncthreads();

#pragma unroll
        for (int k = 0; k < 16; k++) {
            float a[8], b[8];
            *(float4*)&a[0] = *(const float4*)&As[k][tr * 8];
            *(float4*)&a[4] = *(const float4*)&As[k][tr * 8 + 4];
            *(float4*)&b[0] = *(const float4*)&Bs[k][tc * 8];
            *(float4*)&b[4] = *(const float4*)&Bs[k][tc * 8 + 4];
#pragma unroll
            for (int i = 0; i < 8; i++)
#pragma unroll
                for (int j = 0; j < 8; j++)
                    acc[i][j] += a[i] * b[j];
        }
        __syncthreads();
    }

    const int row0 = by * 128 + tr * 8;
    const int col0 = bx * 128 + tc * 8;
#pragma unroll
    for (int i = 0; i < 8; i++) {
        float* cp = C + (size_t)(row0 + i) * N + col0;
#pragma unroll
        for (int j = 0; j < 8; j++) {
            float v = acc[i][j] + bias[col0 + j];
            if (relu) v = fmaxf(v, 0.f);
            acc[i][j] = v;
        }
        *(float4*)(cp)     = *(float4*)&acc[i][0];
        *(float4*)(cp + 4) = *(float4*)&acc[i][4];
    }
}

// ---------------------------------------------------------------------------
// RoPE angle table (double precision to match fp32 reference within ulps)
// ---------------------------------------------------------------------------
__global__ void rope_table_kernel()
{
    int idx = blockIdx.x * blockDim.x + threadIdx.x;   // 32768
    int s = idx >> 5, i = idx & 31;
    double inv = exp(-((double)(2 * i) / 64.0) * log(10000.0));
    double a   = (double)s * inv;
    g_sin[idx] = (float)sin(a);
    g_cos[idx] = (float)cos(a);
}

// RoPE applied in place to q and k slices of qkv.
// grid = TOK blocks, 256 threads = 8 heads x 32 pairs.
__global__ void __launch_bounds__(256)
rope_kernel(float* __restrict__ qkv)
{
    const int token = blockIdx.x;          // b*S + s
    const int s = token & (Sn - 1);
    const int t = threadIdx.x;
    const int h = t >> 5;                  // 0..7
    const int i = t & 31;                  // pair index 0..31
    const float sn = g_sin[s * 32 + i];
    const float cs = g_cos[s * 32 + i];
#pragma unroll
    for (int part = 0; part < 2; part++) { // 0 = q, 1 = k
        float* base = qkv + ((size_t)token * 3 + part) * Dn + h * HDn;
        float x1 = base[i], x2 = base[i + 32];
        base[i]      = x1 * cs - x2 * sn;
        base[i + 32] = x1 * sn + x2 * cs;
    }
}

// ---------------------------------------------------------------------------
// Flash attention: per-(b, h, 64-query tile) block, BK=32, online softmax.
// 256 threads as 16x16 grid; per-thread 4 q-rows x (2 k-cols / 4 d-cols).
// Output written directly in (B, S, H, HD) layout.
// ---------------------------------------------------------------------------
__global__ void __launch_bounds__(256)
flash_attn(const float* __restrict__ qkv, float* __restrict__ O)
{
    __shared__ float Qs[64 * 64];   // [d][q]
    __shared__ float Ks[64 * 32];   // [d][k]
    __shared__ float Vs[32 * 64];   // [k][d]
    __shared__ float Ps[32 * 64];   // [k][q]

    const int t  = threadIdx.x;
    const int ty = t >> 4;          // 0..15: q rows ty*4..+3
    const int tx = t & 15;          // 0..15
    const int qt = blockIdx.x, h = blockIdx.y, b = blockIdx.z;
    const int q0 = qt * 64;

    // Load Q tile transposed into Qs[d][q]
    const float* Qg = qkv + ((size_t)(b * Sn + q0) * 3) * Dn + h * HDn;
#pragma unroll
    for (int u = 0; u < 4; u++) {
        int idx = t + u * 256;                    // 1024 float4
        int row = idx >> 4, c4 = (idx & 15) << 2;
        float4 v = *(const float4*)(Qg + (size_t)row * (3 * Dn) + c4);
        Qs[(c4 + 0) * 64 + row] = v.x;
        Qs[(c4 + 1) * 64 + row] = v.y;
        Qs[(c4 + 2) * 64 + row] = v.z;
        Qs[(c4 + 3) * 64 + row] = v.w;
    }

    float m[4], l[4], o[4][4];
#pragma unroll
    for (int i = 0; i < 4; i++) {
        m[i] = -INFINITY; l[i] = 0.f;
#pragma unroll
        for (int j = 0; j < 4; j++) o[i][j] = 0.f;
    }

    for (int k0 = 0; k0 < Sn; k0 += 32) {
        const float* Kg = qkv + ((size_t)(b * Sn + k0) * 3 + 1) * Dn + h * HDn;
        const float* Vg = qkv + ((size_t)(b * Sn + k0) * 3 + 2) * Dn + h * HDn;
        __syncthreads();   // protect Qs (first iter) / Ks,Vs reuse (later iters)
#pragma unroll
        for (int u = 0; u < 2; u++) {
            int idx = t + u * 256;                // 512 float4
            int row = idx >> 4, c4 = (idx & 15) << 2;
            float4 kv = *(const float4*)(Kg + (size_t)row * (3 * Dn) + c4);
            Ks[(c4 + 0) * 32 + row] = kv.x;
            Ks[(c4 + 1) * 32 + row] = kv.y;
            Ks[(c4 + 2) * 32 + row] = kv.z;
            Ks[(c4 + 3) * 32 + row] = kv.w;
            float4 vv = *(const float4*)(Vg + (size_t)row * (3 * Dn) + c4);
            *(float4*)&Vs[row * 64 + c4] = vv;
        }
        __syncthreads();

        // S = Q K^T (per-thread 4x2)
        float s[4][2] = {{0.f,0.f},{0.f,0.f},{0.f,0.f},{0.f,0.f}};
#pragma unroll
        for (int d = 0; d < 64; d++) {
            float a[4];
            *(float4*)a = *(const float4*)&Qs[d * 64 + ty * 4];
            float b0 = Ks[d * 32 + tx * 2];
            float b1 = Ks[d * 32 + tx * 2 + 1];
#pragma unroll
            for (int i = 0; i < 4; i++) {
                s[i][0] += a[i] * b0;
                s[i][1] += a[i] * b1;
            }
        }

        // Online softmax update (each q-row reduces over its 16-lane group:
        // threads with equal ty are lanes (ty%2)*16..+15 of one warp)
#pragma unroll
        for (int i = 0; i < 4; i++) {
            float s0 = s[i][0] * 0.125f;   // 1/sqrt(64)
            float s1 = s[i][1] * 0.125f;
            float lm = fmaxf(s0, s1);
#pragma unroll
            for (int off = 1; off < 16; off <<= 1)
                lm = fmaxf(lm, __shfl_xor_sync(0xffffffffu, lm, off));
            float mn    = fmaxf(m[i], lm);
            float alpha = __expf(m[i] - mn);
            float p0    = __expf(s0 - mn);
            float p1    = __expf(s1 - mn);
            float rs    = p0 + p1;
#pragma unroll
            for (int off = 1; off < 16; off <<= 1)
                rs += __shfl_xor_sync(0xffffffffu, rs, off);
            l[i] = l[i] * alpha + rs;
            m[i] = mn;
#pragma unroll
            for (int j = 0; j < 4; j++) o[i][j] *= alpha;
            Ps[(tx * 2 + 0) * 64 + ty * 4 + i] = p0;
            Ps[(tx * 2 + 1) * 64 + ty * 4 + i] = p1;
        }
        __syncthreads();

        // O += P V (per-thread 4x4)
#pragma unroll
        for (int k = 0; k < 32; k++) {
            float a[4], v[4];
            *(float4*)a = *(const float4*)&Ps[k * 64 + ty * 4];
            *(float4*)v = *(const float4*)&Vs[k * 64 + tx * 4];
#pragma unroll
            for (int i = 0; i < 4; i++)
#pragma unroll
                for (int j = 0; j < 4; j++)
                    o[i][j] += a[i] * v[j];
        }
    }

#pragma unroll
    for (int i = 0; i < 4; i++) {
        float inv = 1.f / l[i];
        float4 ov = make_float4(o[i][0] * inv, o[i][1] * inv,
                                o[i][2] * inv, o[i][3] * inv);
        *(float4*)(O + (size_t)(b * Sn + q0 + ty * 4 + i) * Dn + h * HDn + tx * 4) = ov;
    }
}

// ---------------------------------------------------------------------------
// LayerNorm(X + Y) * g + b  (exact two-pass mean/var, D = 512)
// ---------------------------------------------------------------------------
__global__ void __launch_bounds__(256)
ln_residual(const float* __restrict__ X, const float* __restrict__ Y,
            const float* __restrict__ g, const float* __restrict__ bta,
            float* __restrict__ out)
{
    __shared__ float red[8];
    const int row = blockIdx.x, t = threadIdx.x;
    const float* x = X + (size_t)row * Dn;
    const float* y = Y + (size_t)row * Dn;

    float v0 = x[t] + y[t];
    float v1 = x[t + 256] + y[t + 256];

    const int lane = t & 31, wid = t >> 5;
    float s = v0 + v1;
#pragma unroll
    for (int off = 16; off; off >>= 1) s += __shfl_xor_sync(0xffffffffu, s, off);
    if (!lane) red[wid] = s;
    __syncthreads();
    float mean = 0.f;
#pragma unroll
    for (int i = 0; i < 8; i++) mean += red[i];
    mean *= (1.f / 512.f);
    __syncthreads();

    float d0 = v0 - mean, d1 = v1 - mean;
    float ss = d0 * d0 + d1 * d1;
#pragma unroll
    for (int off = 16; off; off >>= 1) ss += __shfl_xor_sync(0xffffffffu, ss, off);
    if (!lane) red[wid] = ss;
    __syncthreads();
    float var = 0.f;
#pragma unroll
    for (int i = 0; i < 8; i++) var += red[i];
    var *= (1.f / 512.f);
    float inv = rsqrtf(var + 1e-5f);

    out[(size_t)row * Dn + t]       = d0 * inv * g[t]       + bta[t];
    out[(size_t)row * Dn + t + 256] = d1 * inv * g[t + 256] + bta[t + 256];
}

// ---------------------------------------------------------------------------
// Launch sequence
// ---------------------------------------------------------------------------
extern "C" void kernel_launch(void* const* d_in, const int* in_sizes, int n_in,
                              void* d_out, int out_size)
{
    const float* x      = (const float*)d_in[0];
    const float* w_in   = (const float*)d_in[1];
    const float* b_in   = (const float*)d_in[2];
    const float* w_qkv  = (const float*)d_in[3];
    const float* b_qkv  = (const float*)d_in[4];
    const float* w_out  = (const float*)d_in[5];
    const float* b_out  = (const float*)d_in[6];
    const float* w_ffn1 = (const float*)d_in[7];
    const float* b_ffn1 = (const float*)d_in[8];
    const float* w_ffn2 = (const float*)d_in[9];
    const float* b_ffn2 = (const float*)d_in[10];
    const float* g1     = (const float*)d_in[11];
    const float* bn1    = (const float*)d_in[12];
    const float* g2     = (const float*)d_in[13];
    const float* bn2    = (const float*)d_in[14];
    float* out = (float*)d_out;

    float *h, *qkv, *attn, *oprj, *h2, *f1, *f2;
    cudaGetSymbolAddress((void**)&h,    g_h);
    cudaGetSymbolAddress((void**)&qkv,  g_qkv);
    cudaGetSymbolAddress((void**)&attn, g_attn);
    cudaGetSymbolAddress((void**)&oprj, g_oprj);
    cudaGetSymbolAddress((void**)&h2,   g_h2);
    cudaGetSymbolAddress((void**)&f1,   g_f1);
    cudaGetSymbolAddress((void**)&f2,   g_f2);

    // 1. h = x @ w_in + b_in                         [16384,1280]x[1280,512]
    sgemm_bias<<<dim3(4, 128), 256>>>(x, w_in, b_in, h, TOK, Dn, CIN, 0);
    // 2. qkv = h @ w_qkv + b_qkv                     [16384,512]x[512,1536]
    sgemm_bias<<<dim3(12, 128), 256>>>(h, w_qkv, b_qkv, qkv, TOK, 3 * Dn, Dn, 0);
    // 3. RoPE table + apply to q, k in place
    rope_table_kernel<<<128, 256>>>();
    rope_kernel<<<TOK, 256>>>(qkv);
    // 4. attention -> (B,S,H,HD) layout
    flash_attn<<<dim3(Sn / 64, Hn, Bn), 256>>>(qkv, attn);
    // 5. o @ w_out + b_out
    sgemm_bias<<<dim3(4, 128), 256>>>(attn, w_out, b_out, oprj, TOK, Dn, Dn, 0);
    // 6. h2 = LN(h + o)
    ln_residual<<<TOK, 256>>>(h, oprj, g1, bn1, h2);
    // 7. f1 = relu(h2 @ w_ffn1 + b_ffn1)             [16384,512]x[512,2048]
    sgemm_bias<<<dim3(16, 128), 256>>>(h2, w_ffn1, b_ffn1, f1, TOK, 4 * Dn, Dn, 1);
    // 8. f2 = f1 @ w_ffn2 + b_ffn2                   [16384,2048]x[2048,512]
    sgemm_bias<<<dim3(4, 128), 256>>>(f1, w_ffn2, b_ffn2, f2, TOK, Dn, 4 * Dn, 0);
    // 9. out = LN(h2 + f2)
    ln_residual<<<TOK, 256>>>(h2, f2, g2, bn2, out);
}

// round 4
// speedup vs baseline: 1.5838x; 1.5838x over previous
#include <cuda_runtime.h>
#include <cuda_bf16.h>
#include <math.h>

// Problem shape constants
#define Bn   16
#define Sn   1024
#define CIN  1280
#define Dn   512
#define Hn   8
#define HDn  64
#define TOK  (Bn*Sn)   // 16384

// ---------------------------------------------------------------------------
// Static scratch (no cudaMalloc allowed)
// ---------------------------------------------------------------------------
__device__ float g_h   [TOK * Dn];
__device__ float g_qkv [TOK * 3 * Dn];
__device__ float g_attn[TOK * Dn];
__device__ float g_oprj[TOK * Dn];
__device__ float g_h2  [TOK * Dn];
__device__ float g_f1  [TOK * 4 * Dn];
__device__ float g_f2  [TOK * Dn];
__device__ float g_sin [Sn * 32];
__device__ float g_cos [Sn * 32];

// bf16 hi/lo split buffers (activations + weights)
__device__ __nv_bfloat16 g_xh  [TOK * CIN],    g_xl  [TOK * CIN];
__device__ __nv_bfloat16 g_hh  [TOK * Dn],     g_hl  [TOK * Dn];
__device__ __nv_bfloat16 g_ah  [TOK * Dn],     g_al  [TOK * Dn];
__device__ __nv_bfloat16 g_h2h [TOK * Dn],     g_h2l [TOK * Dn];
__device__ __nv_bfloat16 g_f1h [TOK * 4 * Dn], g_f1l [TOK * 4 * Dn];
__device__ __nv_bfloat16 g_w1h [CIN * Dn],     g_w1l [CIN * Dn];
__device__ __nv_bfloat16 g_wqh [Dn * 3 * Dn],  g_wql [Dn * 3 * Dn];
__device__ __nv_bfloat16 g_woh [Dn * Dn],      g_wol [Dn * Dn];
__device__ __nv_bfloat16 g_wf1h[Dn * 4 * Dn],  g_wf1l[Dn * 4 * Dn];
__device__ __nv_bfloat16 g_wf2h[4 * Dn * Dn],  g_wf2l[4 * Dn * Dn];

// ---------------------------------------------------------------------------
// fp32 -> bf16 hi/lo split conversion (4 elements / thread)
// ---------------------------------------------------------------------------
__global__ void __launch_bounds__(256)
convert_split(const float* __restrict__ in, __nv_bfloat16* __restrict__ hi,
              __nv_bfloat16* __restrict__ lo)
{
    int idx = (blockIdx.x * 256 + threadIdx.x) * 4;
    float4 v = *(const float4*)(in + idx);
    __nv_bfloat16 h0 = __float2bfloat16_rn(v.x);
    __nv_bfloat16 h1 = __float2bfloat16_rn(v.y);
    __nv_bfloat16 h2 = __float2bfloat16_rn(v.z);
    __nv_bfloat16 h3 = __float2bfloat16_rn(v.w);
    __nv_bfloat16 l0 = __float2bfloat16_rn(v.x - __bfloat162float(h0));
    __nv_bfloat16 l1 = __float2bfloat16_rn(v.y - __bfloat162float(h1));
    __nv_bfloat16 l2 = __float2bfloat16_rn(v.z - __bfloat162float(h2));
    __nv_bfloat16 l3 = __float2bfloat16_rn(v.w - __bfloat162float(h3));
    __nv_bfloat162* hp = (__nv_bfloat162*)(hi + idx);
    __nv_bfloat162* lp = (__nv_bfloat162*)(lo + idx);
    hp[0] = __nv_bfloat162(h0, h1);
    hp[1] = __nv_bfloat162(h2, h3);
    lp[0] = __nv_bfloat162(l0, l1);
    lp[1] = __nv_bfloat162(l2, l3);
}

// ---------------------------------------------------------------------------
// Tensor-core GEMM with bf16 2-term split (AhBh + AhBl + AlBh ~ fp32 accuracy)
// C[M,N] = A[M,K] @ B[K,N] + bias (optional ReLU)
// 128x128 CTA tile, BK=32, 256 threads (8 warps: 2 x 4), warp tile 64x32,
// mma.sync m16n8k16 bf16 with fp32 accum.
// ---------------------------------------------------------------------------
#define PADK 40   // bf16 elements per smem row (32 + 8 pad): conflict-free frags

__device__ __forceinline__ void mma16816(float* d, const unsigned* a, const unsigned* b)
{
    asm volatile(
        "mma.sync.aligned.m16n8k16.row.col.f32.bf16.bf16.f32 "
        "{%0,%1,%2,%3},{%4,%5,%6,%7},{%8,%9},{%0,%1,%2,%3};"
        : "+f"(d[0]), "+f"(d[1]), "+f"(d[2]), "+f"(d[3])
        : "r"(a[0]), "r"(a[1]), "r"(a[2]), "r"(a[3]), "r"(b[0]), "r"(b[1]));
}

__global__ void __launch_bounds__(256)
bgemm(const __nv_bfloat16* __restrict__ Ah, const __nv_bfloat16* __restrict__ Al,
      const __nv_bfloat16* __restrict__ Bh, const __nv_bfloat16* __restrict__ Bl,
      const float* __restrict__ bias, float* __restrict__ C,
      int M, int N, int K, int relu)
{
    __shared__ __align__(16) __nv_bfloat16 sAh[128 * PADK];
    __shared__ __align__(16) __nv_bfloat16 sAl[128 * PADK];
    __shared__ __align__(16) __nv_bfloat16 sBh[128 * PADK];
    __shared__ __align__(16) __nv_bfloat16 sBl[128 * PADK];

    const int t    = threadIdx.x;
    const int warp = t >> 5, lane = t & 31;
    const int wm   = warp & 1;            // 0..1  -> m offset wm*64
    const int wn   = warp >> 1;           // 0..3  -> n offset wn*32
    const int g    = lane >> 2;           // group 0..7
    const int tig  = lane & 3;            // thread-in-group
    const int bx   = blockIdx.x, by = blockIdx.y;

    float acc[4][4][4];
#pragma unroll
    for (int mt = 0; mt < 4; mt++)
#pragma unroll
        for (int nt = 0; nt < 4; nt++)
#pragma unroll
            for (int i = 0; i < 4; i++) acc[mt][nt][i] = 0.f;

    for (int k0 = 0; k0 < K; k0 += 32) {
        // --- load A tiles (128 x 32, row-major [m][k]) ---
#pragma unroll
        for (int u = 0; u < 2; u++) {
            int idx = t + u * 256;            // 512 uint4 per version
            int row = idx >> 2, seg = idx & 3;
            size_t go = (size_t)(by * 128 + row) * K + k0 + seg * 8;
            *(uint4*)&sAh[row * PADK + seg * 8] = *(const uint4*)(Ah + go);
            *(uint4*)&sAl[row * PADK + seg * 8] = *(const uint4*)(Al + go);
        }
        // --- load B tiles (32 x 128), store transposed [n][k] ---
#pragma unroll
        for (int u = 0; u < 2; u++) {
            int idx  = t + u * 256;
            int krow = idx >> 4, nseg = idx & 15;
            size_t go = (size_t)(k0 + krow) * N + bx * 128 + nseg * 8;
            union { uint4 u4; __nv_bfloat16 b[8]; } th, tl;
            th.u4 = *(const uint4*)(Bh + go);
            tl.u4 = *(const uint4*)(Bl + go);
#pragma unroll
            for (int j = 0; j < 8; j++) {
                sBh[(nseg * 8 + j) * PADK + krow] = th.b[j];
                sBl[(nseg * 8 + j) * PADK + krow] = tl.b[j];
            }
        }
        __syncthreads();

#pragma unroll
        for (int s = 0; s < 2; s++) {
            const int kk = s * 16;
            unsigned ah[4][4], al[4][4], bh[4][2], bl[4][2];
#pragma unroll
            for (int mt = 0; mt < 4; mt++) {
                int r = wm * 64 + mt * 16;
                ah[mt][0] = *(unsigned*)&sAh[(r + g    ) * PADK + kk     + tig * 2];
                ah[mt][1] = *(unsigned*)&sAh[(r + g + 8) * PADK + kk     + tig * 2];
                ah[mt][2] = *(unsigned*)&sAh[(r + g    ) * PADK + kk + 8 + tig * 2];
                ah[mt][3] = *(unsigned*)&sAh[(r + g + 8) * PADK + kk + 8 + tig * 2];
                al[mt][0] = *(unsigned*)&sAl[(r + g    ) * PADK + kk     + tig * 2];
                al[mt][1] = *(unsigned*)&sAl[(r + g + 8) * PADK + kk     + tig * 2];
                al[mt][2] = *(unsigned*)&sAl[(r + g    ) * PADK + kk + 8 + tig * 2];
                al[mt][3] = *(unsigned*)&sAl[(r + g + 8) * PADK + kk + 8 + tig * 2];
            }
#pragma unroll
            for (int nt = 0; nt < 4; nt++) {
                int n = wn * 32 + nt * 8 + g;
                bh[nt][0] = *(unsigned*)&sBh[n * PADK + kk     + tig * 2];
                bh[nt][1] = *(unsigned*)&sBh[n * PADK + kk + 8 + tig * 2];
                bl[nt][0] = *(unsigned*)&sBl[n * PADK + kk     + tig * 2];
                bl[nt][1] = *(unsigned*)&sBl[n * PADK + kk + 8 + tig * 2];
            }
#pragma unroll
            for (int mt = 0; mt < 4; mt++)
#pragma unroll
                for (int nt = 0; nt < 4; nt++) {
                    mma16816(acc[mt][nt], ah[mt], bh[nt]);
                    mma16816(acc[mt][nt], ah[mt], bl[nt]);
                    mma16816(acc[mt][nt], al[mt], bh[nt]);
                }
        }
        __syncthreads();
    }

    // --- epilogue: bias (+ relu), fp32 store ---
#pragma unroll
    for (int mt = 0; mt < 4; mt++) {
        int r0 = by * 128 + wm * 64 + mt * 16 + g;
#pragma unroll
        for (int nt = 0; nt < 4; nt++) {
            int c = bx * 128 + wn * 32 + nt * 8 + tig * 2;
            float b0 = bias[c], b1 = bias[c + 1];
            float v0 = acc[mt][nt][0] + b0, v1 = acc[mt][nt][1] + b1;
            float v2 = acc[mt][nt][2] + b0, v3 = acc[mt][nt][3] + b1;
            if (relu) {
                v0 = fmaxf(v0, 0.f); v1 = fmaxf(v1, 0.f);
                v2 = fmaxf(v2, 0.f); v3 = fmaxf(v3, 0.f);
            }
            *(float2*)(C + (size_t)r0 * N + c)       = make_float2(v0, v1);
            *(float2*)(C + (size_t)(r0 + 8) * N + c) = make_float2(v2, v3);
        }
    }
}

// ---------------------------------------------------------------------------
// RoPE angle table (double precision)
// ---------------------------------------------------------------------------
__global__ void rope_table_kernel()
{
    int idx = blockIdx.x * blockDim.x + threadIdx.x;   // 32768
    int s = idx >> 5, i = idx & 31;
    double inv = exp(-((double)(2 * i) / 64.0) * log(10000.0));
    double a   = (double)s * inv;
    g_sin[idx] = (float)sin(a);
    g_cos[idx] = (float)cos(a);
}

__global__ void __launch_bounds__(256)
rope_kernel(float* __restrict__ qkv)
{
    const int token = blockIdx.x;
    const int s = token & (Sn - 1);
    const int t = threadIdx.x;
    const int h = t >> 5;
    const int i = t & 31;
    const float sn = g_sin[s * 32 + i];
    const float cs = g_cos[s * 32 + i];
#pragma unroll
    for (int part = 0; part < 2; part++) {
        float* base = qkv + ((size_t)token * 3 + part) * Dn + h * HDn;
        float x1 = base[i], x2 = base[i + 32];
        base[i]      = x1 * cs - x2 * sn;
        base[i + 32] = x1 * sn + x2 * cs;
    }
}

// ---------------------------------------------------------------------------
// Flash attention (fp32, unchanged from validated baseline)
// ---------------------------------------------------------------------------
__global__ void __launch_bounds__(256)
flash_attn(const float* __restrict__ qkv, float* __restrict__ O)
{
    __shared__ float Qs[64 * 64];
    __shared__ float Ks[64 * 32];
    __shared__ float Vs[32 * 64];
    __shared__ float Ps[32 * 64];

    const int t  = threadIdx.x;
    const int ty = t >> 4;
    const int tx = t & 15;
    const int qt = blockIdx.x, h = blockIdx.y, b = blockIdx.z;
    const int q0 = qt * 64;

    const float* Qg = qkv + ((size_t)(b * Sn + q0) * 3) * Dn + h * HDn;
#pragma unroll
    for (int u = 0; u < 4; u++) {
        int idx = t + u * 256;
        int row = idx >> 4, c4 = (idx & 15) << 2;
        float4 v = *(const float4*)(Qg + (size_t)row * (3 * Dn) + c4);
        Qs[(c4 + 0) * 64 + row] = v.x;
        Qs[(c4 + 1) * 64 + row] = v.y;
        Qs[(c4 + 2) * 64 + row] = v.z;
        Qs[(c4 + 3) * 64 + row] = v.w;
    }

    float m[4], l[4], o[4][4];
#pragma unroll
    for (int i = 0; i < 4; i++) {
        m[i] = -INFINITY; l[i] = 0.f;
#pragma unroll
        for (int j = 0; j < 4; j++) o[i][j] = 0.f;
    }

    for (int k0 = 0; k0 < Sn; k0 += 32) {
        const float* Kg = qkv + ((size_t)(b * Sn + k0) * 3 + 1) * Dn + h * HDn;
        const float* Vg = qkv + ((size_t)(b * Sn + k0) * 3 + 2) * Dn + h * HDn;
        __syncthreads();
#pragma unroll
        for (int u = 0; u < 2; u++) {
            int idx = t + u * 256;
            int row = idx >> 4, c4 = (idx & 15) << 2;
            float4 kv = *(const float4*)(Kg + (size_t)row * (3 * Dn) + c4);
            Ks[(c4 + 0) * 32 + row] = kv.x;
            Ks[(c4 + 1) * 32 + row] = kv.y;
            Ks[(c4 + 2) * 32 + row] = kv.z;
            Ks[(c4 + 3) * 32 + row] = kv.w;
            float4 vv = *(const float4*)(Vg + (size_t)row * (3 * Dn) + c4);
            *(float4*)&Vs[row * 64 + c4] = vv;
        }
        __syncthreads();

        float s[4][2] = {{0.f,0.f},{0.f,0.f},{0.f,0.f},{0.f,0.f}};
#pragma unroll
        for (int d = 0; d < 64; d++) {
            float a[4];
            *(float4*)a = *(const float4*)&Qs[d * 64 + ty * 4];
            float b0 = Ks[d * 32 + tx * 2];
            float b1 = Ks[d * 32 + tx * 2 + 1];
#pragma unroll
            for (int i = 0; i < 4; i++) {
                s[i][0] += a[i] * b0;
                s[i][1] += a[i] * b1;
            }
        }

#pragma unroll
        for (int i = 0; i < 4; i++) {
            float s0 = s[i][0] * 0.125f;
            float s1 = s[i][1] * 0.125f;
            float lm = fmaxf(s0, s1);
#pragma unroll
            for (int off = 1; off < 16; off <<= 1)
                lm = fmaxf(lm, __shfl_xor_sync(0xffffffffu, lm, off));
            float mn    = fmaxf(m[i], lm);
            float alpha = __expf(m[i] - mn);
            float p0    = __expf(s0 - mn);
            float p1    = __expf(s1 - mn);
            float rs    = p0 + p1;
#pragma unroll
            for (int off = 1; off < 16; off <<= 1)
                rs += __shfl_xor_sync(0xffffffffu, rs, off);
            l[i] = l[i] * alpha + rs;
            m[i] = mn;
#pragma unroll
            for (int j = 0; j < 4; j++) o[i][j] *= alpha;
            Ps[(tx * 2 + 0) * 64 + ty * 4 + i] = p0;
            Ps[(tx * 2 + 1) * 64 + ty * 4 + i] = p1;
        }
        __syncthreads();

#pragma unroll
        for (int k = 0; k < 32; k++) {
            float a[4], v[4];
            *(float4*)a = *(const float4*)&Ps[k * 64 + ty * 4];
            *(float4*)v = *(const float4*)&Vs[k * 64 + tx * 4];
#pragma unroll
            for (int i = 0; i < 4; i++)
#pragma unroll
                for (int j = 0; j < 4; j++)
                    o[i][j] += a[i] * v[j];
        }
    }

#pragma unroll
    for (int i = 0; i < 4; i++) {
        float inv = 1.f / l[i];
        float4 ov = make_float4(o[i][0] * inv, o[i][1] * inv,
                                o[i][2] * inv, o[i][3] * inv);
        *(float4*)(O + (size_t)(b * Sn + q0 + ty * 4 + i) * Dn + h * HDn + tx * 4) = ov;
    }
}

// ---------------------------------------------------------------------------
// LayerNorm(X + Y) * g + b
// ---------------------------------------------------------------------------
__global__ void __launch_bounds__(256)
ln_residual(const float* __restrict__ X, const float* __restrict__ Y,
            const float* __restrict__ g, const float* __restrict__ bta,
            float* __restrict__ out)
{
    __shared__ float red[8];
    const int row = blockIdx.x, t = threadIdx.x;
    const float* x = X + (size_t)row * Dn;
    const float* y = Y + (size_t)row * Dn;

    float v0 = x[t] + y[t];
    float v1 = x[t + 256] + y[t + 256];

    const int lane = t & 31, wid = t >> 5;
    float s = v0 + v1;
#pragma unroll
    for (int off = 16; off; off >>= 1) s += __shfl_xor_sync(0xffffffffu, s, off);
    if (!lane) red[wid] = s;
    __syncthreads();
    float mean = 0.f;
#pragma unroll
    for (int i = 0; i < 8; i++) mean += red[i];
    mean *= (1.f / 512.f);
    __syncthreads();

    float d0 = v0 - mean, d1 = v1 - mean;
    float ss = d0 * d0 + d1 * d1;
#pragma unroll
    for (int off = 16; off; off >>= 1) ss += __shfl_xor_sync(0xffffffffu, ss, off);
    if (!lane) red[wid] = ss;
    __syncthreads();
    float var = 0.f;
#pragma unroll
    for (int i = 0; i < 8; i++) var += red[i];
    var *= (1.f / 512.f);
    float inv = rsqrtf(var + 1e-5f);

    out[(size_t)row * Dn + t]       = d0 * inv * g[t]       + bta[t];
    out[(size_t)row * Dn + t + 256] = d1 * inv * g[t + 256] + bta[t + 256];
}

// ---------------------------------------------------------------------------
// Launch sequence
// ---------------------------------------------------------------------------
static inline void conv(const float* in, __nv_bfloat16* hi, __nv_bfloat16* lo, int n)
{
    convert_split<<<n / 1024, 256>>>(in, hi, lo);
}

extern "C" void kernel_launch(void* const* d_in, const int* in_sizes, int n_in,
                              void* d_out, int out_size)
{
    const float* x      = (const float*)d_in[0];
    const float* w_in   = (const float*)d_in[1];
    const float* b_in   = (const float*)d_in[2];
    const float* w_qkv  = (const float*)d_in[3];
    const float* b_qkv  = (const float*)d_in[4];
    const float* w_out  = (const float*)d_in[5];
    const float* b_out  = (const float*)d_in[6];
    const float* w_ffn1 = (const float*)d_in[7];
    const float* b_ffn1 = (const float*)d_in[8];
    const float* w_ffn2 = (const float*)d_in[9];
    const float* b_ffn2 = (const float*)d_in[10];
    const float* g1     = (const float*)d_in[11];
    const float* bn1    = (const float*)d_in[12];
    const float* g2     = (const float*)d_in[13];
    const float* bn2    = (const float*)d_in[14];
    float* out = (float*)d_out;

    float *h, *qkv, *attn, *oprj, *h2, *f1, *f2;
    cudaGetSymbolAddress((void**)&h,    g_h);
    cudaGetSymbolAddress((void**)&qkv,  g_qkv);
    cudaGetSymbolAddress((void**)&attn, g_attn);
    cudaGetSymbolAddress((void**)&oprj, g_oprj);
    cudaGetSymbolAddress((void**)&h2,   g_h2);
    cudaGetSymbolAddress((void**)&f1,   g_f1);
    cudaGetSymbolAddress((void**)&f2,   g_f2);

    __nv_bfloat16 *xh, *xl, *hh, *hl, *ah, *al, *h2h, *h2l, *f1h, *f1l;
    __nv_bfloat16 *w1h, *w1l, *wqh, *wql, *woh, *wol, *wf1h, *wf1l, *wf2h, *wf2l;
    cudaGetSymbolAddress((void**)&xh,  g_xh);   cudaGetSymbolAddress((void**)&xl,  g_xl);
    cudaGetSymbolAddress((void**)&hh,  g_hh);   cudaGetSymbolAddress((void**)&hl,  g_hl);
    cudaGetSymbolAddress((void**)&ah,  g_ah);   cudaGetSymbolAddress((void**)&al,  g_al);
    cudaGetSymbolAddress((void**)&h2h, g_h2h);  cudaGetSymbolAddress((void**)&h2l, g_h2l);
    cudaGetSymbolAddress((void**)&f1h, g_f1h);  cudaGetSymbolAddress((void**)&f1l, g_f1l);
    cudaGetSymbolAddress((void**)&w1h, g_w1h);  cudaGetSymbolAddress((void**)&w1l, g_w1l);
    cudaGetSymbolAddress((void**)&wqh, g_wqh);  cudaGetSymbolAddress((void**)&wql, g_wql);
    cudaGetSymbolAddress((void**)&woh, g_woh);  cudaGetSymbolAddress((void**)&wol, g_wol);
    cudaGetSymbolAddress((void**)&wf1h, g_wf1h); cudaGetSymbolAddress((void**)&wf1l, g_wf1l);
    cudaGetSymbolAddress((void**)&wf2h, g_wf2h); cudaGetSymbolAddress((void**)&wf2l, g_wf2l);

    // Split conversions (weights + x)
    conv(x,      xh,  xl,  TOK * CIN);
    conv(w_in,   w1h, w1l, CIN * Dn);
    conv(w_qkv,  wqh, wql, Dn * 3 * Dn);
    conv(w_out,  woh, wol, Dn * Dn);
    conv(w_ffn1, wf1h, wf1l, Dn * 4 * Dn);
    conv(w_ffn2, wf2h, wf2l, 4 * Dn * Dn);

    // 1. h = x @ w_in + b_in
    bgemm<<<dim3(4, 128), 256>>>(xh, xl, w1h, w1l, b_in, h, TOK, Dn, CIN, 0);
    conv(h, hh, hl, TOK * Dn);
    // 2. qkv = h @ w_qkv + b_qkv
    bgemm<<<dim3(12, 128), 256>>>(hh, hl, wqh, wql, b_qkv, qkv, TOK, 3 * Dn, Dn, 0);
    // 3. RoPE
    rope_table_kernel<<<128, 256>>>();
    rope_kernel<<<TOK, 256>>>(qkv);
    // 4. attention (fp32)
    flash_attn<<<dim3(Sn / 64, Hn, Bn), 256>>>(qkv, attn);
    // 5. o @ w_out + b_out
    conv(attn, ah, al, TOK * Dn);
    bgemm<<<dim3(4, 128), 256>>>(ah, al, woh, wol, b_out, oprj, TOK, Dn, Dn, 0);
    // 6. h2 = LN(h + o)
    ln_residual<<<TOK, 256>>>(h, oprj, g1, bn1, h2);
    conv(h2, h2h, h2l, TOK * Dn);
    // 7. f1 = relu(h2 @ w_ffn1 + b_ffn1)
    bgemm<<<dim3(16, 128), 256>>>(h2h, h2l, wf1h, wf1l, b_ffn1, f1, TOK, 4 * Dn, Dn, 1);
    conv(f1, f1h, f1l, TOK * 4 * Dn);
    // 8. f2 = f1 @ w_ffn2 + b_ffn2
    bgemm<<<dim3(4, 128), 256>>>(f1h, f1l, wf2h, wf2l, b_ffn2, f2, TOK, Dn, 4 * Dn, 0);
    // 9. out = LN(h2 + f2)
    ln_residual<<<TOK, 256>>>(h2, f2, g2, bn2, out);
}

// round 5
// speedup vs baseline: 1.9682x; 1.2427x over previous
#include <cuda_runtime.h>
#include <cuda_bf16.h>
#include <math.h>

// Problem shape constants
#define Bn   16
#define Sn   1024
#define CIN  1280
#define Dn   512
#define Hn   8
#define HDn  64
#define TOK  (Bn*Sn)   // 16384

// ---------------------------------------------------------------------------
// Static scratch (no cudaMalloc allowed)
// ---------------------------------------------------------------------------
__device__ float g_h   [TOK * Dn];
__device__ float g_qkv [TOK * 3 * Dn];
__device__ float g_attn[TOK * Dn];
__device__ float g_oprj[TOK * Dn];
__device__ float g_h2  [TOK * Dn];
__device__ float g_f1  [TOK * 4 * Dn];
__device__ float g_f2  [TOK * Dn];
__device__ float g_sin [Sn * 32];
__device__ float g_cos [Sn * 32];

// bf16 hi/lo split buffers (activations + weights)
__device__ __nv_bfloat16 g_xh  [TOK * CIN],    g_xl  [TOK * CIN];
__device__ __nv_bfloat16 g_hh  [TOK * Dn],     g_hl  [TOK * Dn];
__device__ __nv_bfloat16 g_ah  [TOK * Dn],     g_al  [TOK * Dn];
__device__ __nv_bfloat16 g_h2h [TOK * Dn],     g_h2l [TOK * Dn];
__device__ __nv_bfloat16 g_f1h [TOK * 4 * Dn], g_f1l [TOK * 4 * Dn];
__device__ __nv_bfloat16 g_w1h [CIN * Dn],     g_w1l [CIN * Dn];
__device__ __nv_bfloat16 g_wqh [Dn * 3 * Dn],  g_wql [Dn * 3 * Dn];
__device__ __nv_bfloat16 g_woh [Dn * Dn],      g_wol [Dn * Dn];
__device__ __nv_bfloat16 g_wf1h[Dn * 4 * Dn],  g_wf1l[Dn * 4 * Dn];
__device__ __nv_bfloat16 g_wf2h[4 * Dn * Dn],  g_wf2l[4 * Dn * Dn];

// per-head bf16 hi/lo Q/K/V (RoPE applied), layout [b][h][s][d]
__device__ __nv_bfloat16 g_qheadh[TOK * Dn], g_qheadl[TOK * Dn];
__device__ __nv_bfloat16 g_kheadh[TOK * Dn], g_kheadl[TOK * Dn];
__device__ __nv_bfloat16 g_vheadh[TOK * Dn], g_vheadl[TOK * Dn];

// ---------------------------------------------------------------------------
// fp32 -> bf16 hi/lo split conversion (4 elements / thread)
// ---------------------------------------------------------------------------
__global__ void __launch_bounds__(256)
convert_split(const float* __restrict__ in, __nv_bfloat16* __restrict__ hi,
              __nv_bfloat16* __restrict__ lo)
{
    int idx = (blockIdx.x * 256 + threadIdx.x) * 4;
    float4 v = *(const float4*)(in + idx);
    __nv_bfloat16 h0 = __float2bfloat16_rn(v.x);
    __nv_bfloat16 h1 = __float2bfloat16_rn(v.y);
    __nv_bfloat16 h2 = __float2bfloat16_rn(v.z);
    __nv_bfloat16 h3 = __float2bfloat16_rn(v.w);
    __nv_bfloat16 l0 = __float2bfloat16_rn(v.x - __bfloat162float(h0));
    __nv_bfloat16 l1 = __float2bfloat16_rn(v.y - __bfloat162float(h1));
    __nv_bfloat16 l2 = __float2bfloat16_rn(v.z - __bfloat162float(h2));
    __nv_bfloat16 l3 = __float2bfloat16_rn(v.w - __bfloat162float(h3));
    __nv_bfloat162* hp = (__nv_bfloat162*)(hi + idx);
    __nv_bfloat162* lp = (__nv_bfloat162*)(lo + idx);
    hp[0] = __nv_bfloat162(h0, h1);
    hp[1] = __nv_bfloat162(h2, h3);
    lp[0] = __nv_bfloat162(l0, l1);
    lp[1] = __nv_bfloat162(l2, l3);
}

// ---------------------------------------------------------------------------
// mma.sync m16n8k16 bf16 (validated in R4)
// ---------------------------------------------------------------------------
__device__ __forceinline__ void mma16816(float* d, const unsigned* a, const unsigned* b)
{
    asm volatile(
        "mma.sync.aligned.m16n8k16.row.col.f32.bf16.bf16.f32 "
        "{%0,%1,%2,%3},{%4,%5,%6,%7},{%8,%9},{%0,%1,%2,%3};"
        : "+f"(d[0]), "+f"(d[1]), "+f"(d[2]), "+f"(d[3])
        : "r"(a[0]), "r"(a[1]), "r"(a[2]), "r"(a[3]), "r"(b[0]), "r"(b[1]));
}

// ---------------------------------------------------------------------------
// Tensor-core GEMM with bf16 2-term split (unchanged from R4 — validated)
// ---------------------------------------------------------------------------
#define PADK 40

__global__ void __launch_bounds__(256)
bgemm(const __nv_bfloat16* __restrict__ Ah, const __nv_bfloat16* __restrict__ Al,
      const __nv_bfloat16* __restrict__ Bh, const __nv_bfloat16* __restrict__ Bl,
      const float* __restrict__ bias, float* __restrict__ C,
      int M, int N, int K, int relu)
{
    __shared__ __align__(16) __nv_bfloat16 sAh[128 * PADK];
    __shared__ __align__(16) __nv_bfloat16 sAl[128 * PADK];
    __shared__ __align__(16) __nv_bfloat16 sBh[128 * PADK];
    __shared__ __align__(16) __nv_bfloat16 sBl[128 * PADK];

    const int t    = threadIdx.x;
    const int warp = t >> 5, lane = t & 31;
    const int wm   = warp & 1;
    const int wn   = warp >> 1;
    const int g    = lane >> 2;
    const int tig  = lane & 3;
    const int bx   = blockIdx.x, by = blockIdx.y;

    float acc[4][4][4];
#pragma unroll
    for (int mt = 0; mt < 4; mt++)
#pragma unroll
        for (int nt = 0; nt < 4; nt++)
#pragma unroll
            for (int i = 0; i < 4; i++) acc[mt][nt][i] = 0.f;

    for (int k0 = 0; k0 < K; k0 += 32) {
#pragma unroll
        for (int u = 0; u < 2; u++) {
            int idx = t + u * 256;
            int row = idx >> 2, seg = idx & 3;
            size_t go = (size_t)(by * 128 + row) * K + k0 + seg * 8;
            *(uint4*)&sAh[row * PADK + seg * 8] = *(const uint4*)(Ah + go);
            *(uint4*)&sAl[row * PADK + seg * 8] = *(const uint4*)(Al + go);
        }
#pragma unroll
        for (int u = 0; u < 2; u++) {
            int idx  = t + u * 256;
            int krow = idx >> 4, nseg = idx & 15;
            size_t go = (size_t)(k0 + krow) * N + bx * 128 + nseg * 8;
            union { uint4 u4; __nv_bfloat16 b[8]; } th, tl;
            th.u4 = *(const uint4*)(Bh + go);
            tl.u4 = *(const uint4*)(Bl + go);
#pragma unroll
            for (int j = 0; j < 8; j++) {
                sBh[(nseg * 8 + j) * PADK + krow] = th.b[j];
                sBl[(nseg * 8 + j) * PADK + krow] = tl.b[j];
            }
        }
        __syncthreads();

#pragma unroll
        for (int s = 0; s < 2; s++) {
            const int kk = s * 16;
            unsigned ah[4][4], al[4][4], bh[4][2], bl[4][2];
#pragma unroll
            for (int mt = 0; mt < 4; mt++) {
                int r = wm * 64 + mt * 16;
                ah[mt][0] = *(unsigned*)&sAh[(r + g    ) * PADK + kk     + tig * 2];
                ah[mt][1] = *(unsigned*)&sAh[(r + g + 8) * PADK + kk     + tig * 2];
                ah[mt][2] = *(unsigned*)&sAh[(r + g    ) * PADK + kk + 8 + tig * 2];
                ah[mt][3] = *(unsigned*)&sAh[(r + g + 8) * PADK + kk + 8 + tig * 2];
                al[mt][0] = *(unsigned*)&sAl[(r + g    ) * PADK + kk     + tig * 2];
                al[mt][1] = *(unsigned*)&sAl[(r + g + 8) * PADK + kk     + tig * 2];
                al[mt][2] = *(unsigned*)&sAl[(r + g    ) * PADK + kk + 8 + tig * 2];
                al[mt][3] = *(unsigned*)&sAl[(r + g + 8) * PADK + kk + 8 + tig * 2];
            }
#pragma unroll
            for (int nt = 0; nt < 4; nt++) {
                int n = wn * 32 + nt * 8 + g;
                bh[nt][0] = *(unsigned*)&sBh[n * PADK + kk     + tig * 2];
                bh[nt][1] = *(unsigned*)&sBh[n * PADK + kk + 8 + tig * 2];
                bl[nt][0] = *(unsigned*)&sBl[n * PADK + kk     + tig * 2];
                bl[nt][1] = *(unsigned*)&sBl[n * PADK + kk + 8 + tig * 2];
            }
#pragma unroll
            for (int mt = 0; mt < 4; mt++)
#pragma unroll
                for (int nt = 0; nt < 4; nt++) {
                    mma16816(acc[mt][nt], ah[mt], bh[nt]);
                    mma16816(acc[mt][nt], ah[mt], bl[nt]);
                    mma16816(acc[mt][nt], al[mt], bh[nt]);
                }
        }
        __syncthreads();
    }

#pragma unroll
    for (int mt = 0; mt < 4; mt++) {
        int r0 = by * 128 + wm * 64 + mt * 16 + g;
#pragma unroll
        for (int nt = 0; nt < 4; nt++) {
            int c = bx * 128 + wn * 32 + nt * 8 + tig * 2;
            float b0 = bias[c], b1 = bias[c + 1];
            float v0 = acc[mt][nt][0] + b0, v1 = acc[mt][nt][1] + b1;
            float v2 = acc[mt][nt][2] + b0, v3 = acc[mt][nt][3] + b1;
            if (relu) {
                v0 = fmaxf(v0, 0.f); v1 = fmaxf(v1, 0.f);
                v2 = fmaxf(v2, 0.f); v3 = fmaxf(v3, 0.f);
            }
            *(float2*)(C + (size_t)r0 * N + c)       = make_float2(v0, v1);
            *(float2*)(C + (size_t)(r0 + 8) * N + c) = make_float2(v2, v3);
        }
    }
}

// ---------------------------------------------------------------------------
// RoPE angle table (double precision)
// ---------------------------------------------------------------------------
__global__ void rope_table_kernel()
{
    int idx = blockIdx.x * blockDim.x + threadIdx.x;   // 32768
    int s = idx >> 5, i = idx & 31;
    double inv = exp(-((double)(2 * i) / 64.0) * log(10000.0));
    double a   = (double)s * inv;
    g_sin[idx] = (float)sin(a);
    g_cos[idx] = (float)cos(a);
}

// ---------------------------------------------------------------------------
// RoPE + split to per-head bf16 hi/lo Q/K/V ([b][h][s][d] layout).
// grid = TOK blocks, 256 threads = 8 heads x 32 pairs.
// ---------------------------------------------------------------------------
__device__ __forceinline__ void split_store(__nv_bfloat16* hi, __nv_bfloat16* lo,
                                            size_t idx, float v)
{
    __nv_bfloat16 h = __float2bfloat16_rn(v);
    hi[idx] = h;
    lo[idx] = __float2bfloat16_rn(v - __bfloat162float(h));
}

__global__ void __launch_bounds__(256)
rope_split(const float* __restrict__ qkv,
           __nv_bfloat16* __restrict__ Qh, __nv_bfloat16* __restrict__ Ql,
           __nv_bfloat16* __restrict__ Kh, __nv_bfloat16* __restrict__ Kl,
           __nv_bfloat16* __restrict__ Vh, __nv_bfloat16* __restrict__ Vl)
{
    const int token = blockIdx.x;
    const int s = token & (Sn - 1);
    const int b = token >> 10;
    const int t = threadIdx.x;
    const int h = t >> 5;
    const int i = t & 31;
    const float sn = g_sin[s * 32 + i];
    const float cs = g_cos[s * 32 + i];
    const size_t dst = (((size_t)b * Hn + h) * Sn + s) * HDn;

    // q
    {
        const float* base = qkv + (size_t)token * (3 * Dn) + h * HDn;
        float x1 = base[i], x2 = base[i + 32];
        split_store(Qh, Ql, dst + i,      x1 * cs - x2 * sn);
        split_store(Qh, Ql, dst + i + 32, x1 * sn + x2 * cs);
    }
    // k
    {
        const float* base = qkv + (size_t)token * (3 * Dn) + Dn + h * HDn;
        float x1 = base[i], x2 = base[i + 32];
        split_store(Kh, Kl, dst + i,      x1 * cs - x2 * sn);
        split_store(Kh, Kl, dst + i + 32, x1 * sn + x2 * cs);
    }
    // v (no rotation)
    {
        const float* base = qkv + (size_t)token * (3 * Dn) + 2 * Dn + h * HDn;
        split_store(Vh, Vl, dst + i,      base[i]);
        split_store(Vh, Vl, dst + i + 32, base[i + 32]);
    }
}

// ---------------------------------------------------------------------------
// Flash attention on tensor cores (bf16 hi/lo split, fp32 accum).
// CTA: 64 queries x full S keys, 4 warps (16 q-rows each), K-tiles of 64.
// ---------------------------------------------------------------------------
#define FPAD 72   // 64 + 8 pad: conflict-free fragment loads

__global__ void __launch_bounds__(128)
flash_attn_mma(const __nv_bfloat16* __restrict__ Qh, const __nv_bfloat16* __restrict__ Ql,
               const __nv_bfloat16* __restrict__ Kh, const __nv_bfloat16* __restrict__ Kl,
               const __nv_bfloat16* __restrict__ Vh, const __nv_bfloat16* __restrict__ Vl,
               float* __restrict__ O)
{
    __shared__ __align__(16) __nv_bfloat16 sKh[64 * FPAD], sKl[64 * FPAD];
    __shared__ __align__(16) __nv_bfloat16 sVh[64 * FPAD], sVl[64 * FPAD];

    const int t    = threadIdx.x;
    const int warp = t >> 5, lane = t & 31;
    const int g    = lane >> 2, tig = lane & 3;
    const int qt   = blockIdx.x, h = blockIdx.y, b = blockIdx.z;
    const int q0   = qt * 64;
    const size_t bh = ((size_t)b * Hn + h) * ((size_t)Sn * HDn);

    // ---- stage Q tile (hi->sKh, lo->sKl), pull a-fragments to registers ----
    {
        const __nv_bfloat16* qgh = Qh + bh + (size_t)q0 * HDn;
        const __nv_bfloat16* qgl = Ql + bh + (size_t)q0 * HDn;
#pragma unroll
        for (int u = 0; u < 4; u++) {
            int idx = t + u * 128;           // 512 uint4
            int row = idx >> 3, seg = idx & 7;
            *(uint4*)&sKh[row * FPAD + seg * 8] = *(const uint4*)(qgh + row * HDn + seg * 8);
            *(uint4*)&sKl[row * FPAD + seg * 8] = *(const uint4*)(qgl + row * HDn + seg * 8);
        }
    }
    __syncthreads();

    unsigned qa_h[4][4], qa_l[4][4];
    const int wr = warp * 16;
#pragma unroll
    for (int kk = 0; kk < 4; kk++) {
        qa_h[kk][0] = *(unsigned*)&sKh[(wr + g    ) * FPAD + kk * 16     + tig * 2];
        qa_h[kk][1] = *(unsigned*)&sKh[(wr + g + 8) * FPAD + kk * 16     + tig * 2];
        qa_h[kk][2] = *(unsigned*)&sKh[(wr + g    ) * FPAD + kk * 16 + 8 + tig * 2];
        qa_h[kk][3] = *(unsigned*)&sKh[(wr + g + 8) * FPAD + kk * 16 + 8 + tig * 2];
        qa_l[kk][0] = *(unsigned*)&sKl[(wr + g    ) * FPAD + kk * 16     + tig * 2];
        qa_l[kk][1] = *(unsigned*)&sKl[(wr + g + 8) * FPAD + kk * 16     + tig * 2];
        qa_l[kk][2] = *(unsigned*)&sKl[(wr + g    ) * FPAD + kk * 16 + 8 + tig * 2];
        qa_l[kk][3] = *(unsigned*)&sKl[(wr + g + 8) * FPAD + kk * 16 + 8 + tig * 2];
    }
    __syncthreads();

    float m0 = -INFINITY, m1 = -INFINITY, l0 = 0.f, l1 = 0.f;
    float oacc[8][4];
#pragma unroll
    for (int nt = 0; nt < 8; nt++)
#pragma unroll
        for (int i = 0; i < 4; i++) oacc[nt][i] = 0.f;

    for (int k0 = 0; k0 < Sn; k0 += 64) {
        // ---- load K tile [k][d] direct; V tile transposed [d][k] ----
#pragma unroll
        for (int u = 0; u < 4; u++) {
            int idx = t + u * 128;
            int row = idx >> 3, seg = idx & 7;
            size_t go = bh + (size_t)(k0 + row) * HDn + seg * 8;
            *(uint4*)&sKh[row * FPAD + seg * 8] = *(const uint4*)(Kh + go);
            *(uint4*)&sKl[row * FPAD + seg * 8] = *(const uint4*)(Kl + go);
            union { uint4 u4; __nv_bfloat16 v[8]; } th, tl;
            th.u4 = *(const uint4*)(Vh + go);
            tl.u4 = *(const uint4*)(Vl + go);
#pragma unroll
            for (int j = 0; j < 8; j++) {
                sVh[(seg * 8 + j) * FPAD + row] = th.v[j];
                sVl[(seg * 8 + j) * FPAD + row] = tl.v[j];
            }
        }
        __syncthreads();

        // ---- S = Q K^T (3-term split) ----
        float sacc[8][4];
#pragma unroll
        for (int nt = 0; nt < 8; nt++)
#pragma unroll
            for (int i = 0; i < 4; i++) sacc[nt][i] = 0.f;

#pragma unroll
        for (int kk = 0; kk < 4; kk++) {
#pragma unroll
            for (int nt = 0; nt < 8; nt++) {
                unsigned bhf[2], blf[2];
                bhf[0] = *(unsigned*)&sKh[(nt * 8 + g) * FPAD + kk * 16     + tig * 2];
                bhf[1] = *(unsigned*)&sKh[(nt * 8 + g) * FPAD + kk * 16 + 8 + tig * 2];
                blf[0] = *(unsigned*)&sKl[(nt * 8 + g) * FPAD + kk * 16     + tig * 2];
                blf[1] = *(unsigned*)&sKl[(nt * 8 + g) * FPAD + kk * 16 + 8 + tig * 2];
                mma16816(sacc[nt], qa_h[kk], bhf);
                mma16816(sacc[nt], qa_h[kk], blf);
                mma16816(sacc[nt], qa_l[kk], bhf);
            }
        }

        // ---- online softmax (rows g and g+8; 4 tig lanes share each row) ----
        float tm0 = -INFINITY, tm1 = -INFINITY;
#pragma unroll
        for (int nt = 0; nt < 8; nt++) {
            sacc[nt][0] *= 0.125f; sacc[nt][1] *= 0.125f;
            sacc[nt][2] *= 0.125f; sacc[nt][3] *= 0.125f;
            tm0 = fmaxf(tm0, fmaxf(sacc[nt][0], sacc[nt][1]));
            tm1 = fmaxf(tm1, fmaxf(sacc[nt][2], sacc[nt][3]));
        }
        tm0 = fmaxf(tm0, __shfl_xor_sync(0xffffffffu, tm0, 1));
        tm0 = fmaxf(tm0, __shfl_xor_sync(0xffffffffu, tm0, 2));
        tm1 = fmaxf(tm1, __shfl_xor_sync(0xffffffffu, tm1, 1));
        tm1 = fmaxf(tm1, __shfl_xor_sync(0xffffffffu, tm1, 2));

        float mn0 = fmaxf(m0, tm0), mn1 = fmaxf(m1, tm1);
        float a0 = __expf(m0 - mn0), a1 = __expf(m1 - mn1);
        m0 = mn0; m1 = mn1;

        float rs0 = 0.f, rs1 = 0.f;
#pragma unroll
        for (int nt = 0; nt < 8; nt++) {
            sacc[nt][0] = __expf(sacc[nt][0] - mn0);
            sacc[nt][1] = __expf(sacc[nt][1] - mn0);
            sacc[nt][2] = __expf(sacc[nt][2] - mn1);
            sacc[nt][3] = __expf(sacc[nt][3] - mn1);
            rs0 += sacc[nt][0] + sacc[nt][1];
            rs1 += sacc[nt][2] + sacc[nt][3];
        }
        rs0 += __shfl_xor_sync(0xffffffffu, rs0, 1);
        rs0 += __shfl_xor_sync(0xffffffffu, rs0, 2);
        rs1 += __shfl_xor_sync(0xffffffffu, rs1, 1);
        rs1 += __shfl_xor_sync(0xffffffffu, rs1, 2);
        l0 = l0 * a0 + rs0;
        l1 = l1 * a1 + rs1;

#pragma unroll
        for (int nt = 0; nt < 8; nt++) {
            oacc[nt][0] *= a0; oacc[nt][1] *= a0;
            oacc[nt][2] *= a1; oacc[nt][3] *= a1;
        }

        // ---- O += P V (P split hi/lo in registers; 3-term) ----
#pragma unroll
        for (int j = 0; j < 4; j++) {
            unsigned pah[4], pal[4];
#pragma unroll
            for (int q = 0; q < 4; q++) {
                int nt = 2 * j + (q >> 1);
                int c0 = (q & 1) * 2;
                float p0 = sacc[nt][c0], p1 = sacc[nt][c0 + 1];
                union { __nv_bfloat162 b2; unsigned u; } hh, ll;
                hh.b2 = __floats2bfloat162_rn(p0, p1);
                float2 hf = __bfloat1622float2(hh.b2);
                ll.b2 = __floats2bfloat162_rn(p0 - hf.x, p1 - hf.y);
                // q index 0: row g, k lo | 1: row g+8, k lo | 2: row g, k hi | 3: row g+8, k hi
                int ai = (q == 0) ? 0 : (q == 1) ? 1 : (q == 2) ? 2 : 3;
                pah[ai] = hh.u; pal[ai] = ll.u;
            }
#pragma unroll
            for (int nt = 0; nt < 8; nt++) {
                unsigned vbh[2], vbl[2];
                vbh[0] = *(unsigned*)&sVh[(nt * 8 + g) * FPAD + j * 16     + tig * 2];
                vbh[1] = *(unsigned*)&sVh[(nt * 8 + g) * FPAD + j * 16 + 8 + tig * 2];
                vbl[0] = *(unsigned*)&sVl[(nt * 8 + g) * FPAD + j * 16     + tig * 2];
                vbl[1] = *(unsigned*)&sVl[(nt * 8 + g) * FPAD + j * 16 + 8 + tig * 2];
                mma16816(oacc[nt], pah, vbh);
                mma16816(oacc[nt], pah, vbl);
                mma16816(oacc[nt], pal, vbh);
            }
        }
        __syncthreads();
    }

    // ---- normalize + store to (B,S,H*HD) fp32 ----
    float inv0 = 1.f / l0, inv1 = 1.f / l1;
    const int gq = q0 + wr + g;
    float* op0 = O + (size_t)(b * Sn + gq) * Dn + h * HDn;
    float* op1 = op0 + (size_t)8 * Dn;
#pragma unroll
    for (int nt = 0; nt < 8; nt++) {
        *(float2*)(op0 + nt * 8 + tig * 2) = make_float2(oacc[nt][0] * inv0, oacc[nt][1] * inv0);
        *(float2*)(op1 + nt * 8 + tig * 2) = make_float2(oacc[nt][2] * inv1, oacc[nt][3] * inv1);
    }
}

// ---------------------------------------------------------------------------
// LayerNorm(X + Y) * g + b
// ---------------------------------------------------------------------------
__global__ void __launch_bounds__(256)
ln_residual(const float* __restrict__ X, const float* __restrict__ Y,
            const float* __restrict__ g, const float* __restrict__ bta,
            float* __restrict__ out)
{
    __shared__ float red[8];
    const int row = blockIdx.x, t = threadIdx.x;
    const float* x = X + (size_t)row * Dn;
    const float* y = Y + (size_t)row * Dn;

    float v0 = x[t] + y[t];
    float v1 = x[t + 256] + y[t + 256];

    const int lane = t & 31, wid = t >> 5;
    float s = v0 + v1;
#pragma unroll
    for (int off = 16; off; off >>= 1) s += __shfl_xor_sync(0xffffffffu, s, off);
    if (!lane) red[wid] = s;
    __syncthreads();
    float mean = 0.f;
#pragma unroll
    for (int i = 0; i < 8; i++) mean += red[i];
    mean *= (1.f / 512.f);
    __syncthreads();

    float d0 = v0 - mean, d1 = v1 - mean;
    float ss = d0 * d0 + d1 * d1;
#pragma unroll
    for (int off = 16; off; off >>= 1) ss += __shfl_xor_sync(0xffffffffu, ss, off);
    if (!lane) red[wid] = ss;
    __syncthreads();
    float var = 0.f;
#pragma unroll
    for (int i = 0; i < 8; i++) var += red[i];
    var *= (1.f / 512.f);
    float inv = rsqrtf(var + 1e-5f);

    out[(size_t)row * Dn + t]       = d0 * inv * g[t]       + bta[t];
    out[(size_t)row * Dn + t + 256] = d1 * inv * g[t + 256] + bta[t + 256];
}

// ---------------------------------------------------------------------------
// Launch sequence
// ---------------------------------------------------------------------------
static inline void conv(const float* in, __nv_bfloat16* hi, __nv_bfloat16* lo, int n)
{
    convert_split<<<n / 1024, 256>>>(in, hi, lo);
}

extern "C" void kernel_launch(void* const* d_in, const int* in_sizes, int n_in,
                              void* d_out, int out_size)
{
    const float* x      = (const float*)d_in[0];
    const float* w_in   = (const float*)d_in[1];
    const float* b_in   = (const float*)d_in[2];
    const float* w_qkv  = (const float*)d_in[3];
    const float* b_qkv  = (const float*)d_in[4];
    const float* w_out  = (const float*)d_in[5];
    const float* b_out  = (const float*)d_in[6];
    const float* w_ffn1 = (const float*)d_in[7];
    const float* b_ffn1 = (const float*)d_in[8];
    const float* w_ffn2 = (const float*)d_in[9];
    const float* b_ffn2 = (const float*)d_in[10];
    const float* g1     = (const float*)d_in[11];
    const float* bn1    = (const float*)d_in[12];
    const float* g2     = (const float*)d_in[13];
    const float* bn2    = (const float*)d_in[14];
    float* out = (float*)d_out;

    float *h, *qkv, *attn, *oprj, *h2, *f1, *f2;
    cudaGetSymbolAddress((void**)&h,    g_h);
    cudaGetSymbolAddress((void**)&qkv,  g_qkv);
    cudaGetSymbolAddress((void**)&attn, g_attn);
    cudaGetSymbolAddress((void**)&oprj, g_oprj);
    cudaGetSymbolAddress((void**)&h2,   g_h2);
    cudaGetSymbolAddress((void**)&f1,   g_f1);
    cudaGetSymbolAddress((void**)&f2,   g_f2);

    __nv_bfloat16 *xh, *xl, *hh, *hl, *ah, *al, *h2h, *h2l, *f1h, *f1l;
    __nv_bfloat16 *w1h, *w1l, *wqh, *wql, *woh, *wol, *wf1h, *wf1l, *wf2h, *wf2l;
    __nv_bfloat16 *qhh, *qhl, *khh, *khl, *vhh, *vhl;
    cudaGetSymbolAddress((void**)&xh,  g_xh);   cudaGetSymbolAddress((void**)&xl,  g_xl);
    cudaGetSymbolAddress((void**)&hh,  g_hh);   cudaGetSymbolAddress((void**)&hl,  g_hl);
    cudaGetSymbolAddress((void**)&ah,  g_ah);   cudaGetSymbolAddress((void**)&al,  g_al);
    cudaGetSymbolAddress((void**)&h2h, g_h2h);  cudaGetSymbolAddress((void**)&h2l, g_h2l);
    cudaGetSymbolAddress((void**)&f1h, g_f1h);  cudaGetSymbolAddress((void**)&f1l, g_f1l);
    cudaGetSymbolAddress((void**)&w1h, g_w1h);  cudaGetSymbolAddress((void**)&w1l, g_w1l);
    cudaGetSymbolAddress((void**)&wqh, g_wqh);  cudaGetSymbolAddress((void**)&wql, g_wql);
    cudaGetSymbolAddress((void**)&woh, g_woh);  cudaGetSymbolAddress((void**)&wol, g_wol);
    cudaGetSymbolAddress((void**)&wf1h, g_wf1h); cudaGetSymbolAddress((void**)&wf1l, g_wf1l);
    cudaGetSymbolAddress((void**)&wf2h, g_wf2h); cudaGetSymbolAddress((void**)&wf2l, g_wf2l);
    cudaGetSymbolAddress((void**)&qhh, g_qheadh); cudaGetSymbolAddress((void**)&qhl, g_qheadl);
    cudaGetSymbolAddress((void**)&khh, g_kheadh); cudaGetSymbolAddress((void**)&khl, g_kheadl);
    cudaGetSymbolAddress((void**)&vhh, g_vheadh); cudaGetSymbolAddress((void**)&vhl, g_vheadl);

    // Split conversions (weights + x)
    conv(x,      xh,  xl,  TOK * CIN);
    conv(w_in,   w1h, w1l, CIN * Dn);
    conv(w_qkv,  wqh, wql, Dn * 3 * Dn);
    conv(w_out,  woh, wol, Dn * Dn);
    conv(w_ffn1, wf1h, wf1l, Dn * 4 * Dn);
    conv(w_ffn2, wf2h, wf2l, 4 * Dn * Dn);

    // 1. h = x @ w_in + b_in
    bgemm<<<dim3(4, 128), 256>>>(xh, xl, w1h, w1l, b_in, h, TOK, Dn, CIN, 0);
    conv(h, hh, hl, TOK * Dn);
    // 2. qkv = h @ w_qkv + b_qkv
    bgemm<<<dim3(12, 128), 256>>>(hh, hl, wqh, wql, b_qkv, qkv, TOK, 3 * Dn, Dn, 0);
    // 3. RoPE + split to per-head bf16
    rope_table_kernel<<<128, 256>>>();
    rope_split<<<TOK, 256>>>(qkv, qhh, qhl, khh, khl, vhh, vhl);
    // 4. attention on tensor cores
    flash_attn_mma<<<dim3(Sn / 64, Hn, Bn), 128>>>(qhh, qhl, khh, khl, vhh, vhl, attn);
    // 5. o @ w_out + b_out
    conv(attn, ah, al, TOK * Dn);
    bgemm<<<dim3(4, 128), 256>>>(ah, al, woh, wol, b_out, oprj, TOK, Dn, Dn, 0);
    // 6. h2 = LN(h + o)
    ln_residual<<<TOK, 256>>>(h, oprj, g1, bn1, h2);
    conv(h2, h2h, h2l, TOK * Dn);
    // 7. f1 = relu(h2 @ w_ffn1 + b_ffn1)
    bgemm<<<dim3(16, 128), 256>>>(h2h, h2l, wf1h, wf1l, b_ffn1, f1, TOK, 4 * Dn, Dn, 1);
    conv(f1, f1h, f1l, TOK * 4 * Dn);
    // 8. f2 = f1 @ w_ffn2 + b_ffn2
    bgemm<<<dim3(4, 128), 256>>>(f1h, f1l, wf2h, wf2l, b_ffn2, f2, TOK, Dn, 4 * Dn, 0);
    // 9. out = LN(h2 + f2)
    ln_residual<<<TOK, 256>>>(h2, f2, g2, bn2, out);
}

// round 13
// speedup vs baseline: 4.2093x; 2.1386x over previous
#include <cuda_runtime.h>
#include <cuda_bf16.h>
#include <math.h>

// Problem shape constants
#define Bn   16
#define Sn   1024
#define CIN  1280
#define Dn   512
#define Hn   8
#define HDn  64
#define TOK  (Bn*Sn)   // 16384

// ---------------------------------------------------------------------------
// Static scratch (no cudaMalloc allowed)
// ---------------------------------------------------------------------------
__device__ float g_h   [TOK * Dn];
__device__ float g_qkv [TOK * 3 * Dn];
__device__ float g_oprj[TOK * Dn];
__device__ float g_h2  [TOK * Dn];
__device__ float g_f2  [TOK * Dn];
__device__ float g_sin [Sn * 32];
__device__ float g_cos [Sn * 32];

// bf16 hi/lo split buffers (activations + weights)
__device__ __nv_bfloat16 g_xh  [TOK * CIN],    g_xl  [TOK * CIN];
__device__ __nv_bfloat16 g_hh  [TOK * Dn],     g_hl  [TOK * Dn];
__device__ __nv_bfloat16 g_ah  [TOK * Dn],     g_al  [TOK * Dn];
__device__ __nv_bfloat16 g_h2h [TOK * Dn],     g_h2l [TOK * Dn];
__device__ __nv_bfloat16 g_f1h [TOK * 4 * Dn], g_f1l [TOK * 4 * Dn];
__device__ __nv_bfloat16 g_w1h [CIN * Dn],     g_w1l [CIN * Dn];
__device__ __nv_bfloat16 g_wqh [Dn * 3 * Dn],  g_wql [Dn * 3 * Dn];
__device__ __nv_bfloat16 g_woh [Dn * Dn],      g_wol [Dn * Dn];
__device__ __nv_bfloat16 g_wf1h[Dn * 4 * Dn],  g_wf1l[Dn * 4 * Dn];
__device__ __nv_bfloat16 g_wf2h[4 * Dn * Dn],  g_wf2l[4 * Dn * Dn];

// per-head bf16 hi/lo Q/K/V (RoPE applied), layout [b][h][s][d]
__device__ __nv_bfloat16 g_qheadh[TOK * Dn], g_qheadl[TOK * Dn];
__device__ __nv_bfloat16 g_kheadh[TOK * Dn], g_kheadl[TOK * Dn];
__device__ __nv_bfloat16 g_vheadh[TOK * Dn], g_vheadl[TOK * Dn];

// ---------------------------------------------------------------------------
// helpers
// ---------------------------------------------------------------------------
__device__ __forceinline__ void mma16816(float* d, const unsigned* a, const unsigned* b)
{
    asm volatile(
        "mma.sync.aligned.m16n8k16.row.col.f32.bf16.bf16.f32 "
        "{%0,%1,%2,%3},{%4,%5,%6,%7},{%8,%9},{%0,%1,%2,%3};"
        : "+f"(d[0]), "+f"(d[1]), "+f"(d[2]), "+f"(d[3])
        : "r"(a[0]), "r"(a[1]), "r"(a[2]), "r"(a[3]), "r"(b[0]), "r"(b[1]));
}

__device__ __forceinline__ void ldsm_x4(unsigned* r, const void* p)
{
    unsigned a = (unsigned)__cvta_generic_to_shared(p);
    asm volatile("ldmatrix.sync.aligned.m8n8.x4.shared.b16 {%0,%1,%2,%3}, [%4];"
                 : "=r"(r[0]), "=r"(r[1]), "=r"(r[2]), "=r"(r[3]) : "r"(a));
}
__device__ __forceinline__ void ldsm_x2(unsigned* r, const void* p)
{
    unsigned a = (unsigned)__cvta_generic_to_shared(p);
    asm volatile("ldmatrix.sync.aligned.m8n8.x2.shared.b16 {%0,%1}, [%2];"
                 : "=r"(r[0]), "=r"(r[1]) : "r"(a));
}
__device__ __forceinline__ void ldsm_x2t(unsigned* r, const void* p)
{
    unsigned a = (unsigned)__cvta_generic_to_shared(p);
    asm volatile("ldmatrix.sync.aligned.m8n8.x2.trans.shared.b16 {%0,%1}, [%2];"
                 : "=r"(r[0]), "=r"(r[1]) : "r"(a));
}

__device__ __forceinline__ void split_store(__nv_bfloat16* hi, __nv_bfloat16* lo,
                                            size_t idx, float v)
{
    __nv_bfloat16 h = __float2bfloat16_rn(v);
    hi[idx] = h;
    lo[idx] = __float2bfloat16_rn(v - __bfloat162float(h));
}

__device__ __forceinline__ void split2_store(__nv_bfloat16* H, __nv_bfloat16* L,
                                             size_t off, float v0, float v1)
{
    __nv_bfloat162 hh = __floats2bfloat162_rn(v0, v1);
    float2 hf = __bfloat1622float2(hh);
    __nv_bfloat162 ll = __floats2bfloat162_rn(v0 - hf.x, v1 - hf.y);
    *(__nv_bfloat162*)(H + off) = hh;
    *(__nv_bfloat162*)(L + off) = ll;
}

// ---------------------------------------------------------------------------
// fp32 -> bf16 hi/lo split conversion (4 elements / thread)
// ---------------------------------------------------------------------------
__global__ void __launch_bounds__(256)
convert_split(const float* __restrict__ in, __nv_bfloat16* __restrict__ hi,
              __nv_bfloat16* __restrict__ lo)
{
    int idx = (blockIdx.x * 256 + threadIdx.x) * 4;
    float4 v = *(const float4*)(in + idx);
    split2_store(hi, lo, idx,     v.x, v.y);
    split2_store(hi, lo, idx + 2, v.z, v.w);
}

// ---------------------------------------------------------------------------
// Tensor-core GEMM, bf16 2-term split (AhBh + AhBl + AlBh).
// 128x128 CTA tile, BK=32, 256 threads (8 warps 2x4), warp tile 64x32.
// A smem [m][k] (PADK), B smem [k][n] natural (PADN); frags via ldmatrix.
// Optional fp32 C and/or bf16 hi/lo split outputs.
// ---------------------------------------------------------------------------
#define PADK 40
#define PADN 136

__global__ void __launch_bounds__(256)
bgemm(const __nv_bfloat16* __restrict__ Ah, const __nv_bfloat16* __restrict__ Al,
      const __nv_bfloat16* __restrict__ Bh, const __nv_bfloat16* __restrict__ Bl,
      const float* __restrict__ bias, float* __restrict__ C,
      __nv_bfloat16* __restrict__ Ch, __nv_bfloat16* __restrict__ Cl,
      int M, int N, int K, int relu)
{
    __shared__ __align__(16) __nv_bfloat16 sAh[128 * PADK];
    __shared__ __align__(16) __nv_bfloat16 sAl[128 * PADK];
    __shared__ __align__(16) __nv_bfloat16 sBh[32 * PADN];
    __shared__ __align__(16) __nv_bfloat16 sBl[32 * PADN];

    const int t    = threadIdx.x;
    const int warp = t >> 5, lane = t & 31;
    const int wm   = warp & 1;
    const int wn   = warp >> 1;
    const int g    = lane >> 2;
    const int tig  = lane & 3;
    const int bx   = blockIdx.x, by = blockIdx.y;
    const int l15  = lane & 15;
    const int lhi  = lane >> 4;          // 0/1: k-halves for A ldmatrix

    float acc[4][4][4];
#pragma unroll
    for (int mt = 0; mt < 4; mt++)
#pragma unroll
        for (int nt = 0; nt < 4; nt++)
#pragma unroll
            for (int i = 0; i < 4; i++) acc[mt][nt][i] = 0.f;

    for (int k0 = 0; k0 < K; k0 += 32) {
        // A tiles: 128x32 row-major, vectorized
#pragma unroll
        for (int u = 0; u < 2; u++) {
            int idx = t + u * 256;
            int row = idx >> 2, seg = idx & 3;
            size_t go = (size_t)(by * 128 + row) * K + k0 + seg * 8;
            *(uint4*)&sAh[row * PADK + seg * 8] = *(const uint4*)(Ah + go);
            *(uint4*)&sAl[row * PADK + seg * 8] = *(const uint4*)(Al + go);
        }
        // B tiles: 32x128 natural [k][n], vectorized
#pragma unroll
        for (int u = 0; u < 2; u++) {
            int idx  = t + u * 256;
            int krow = idx >> 4, nseg = idx & 15;
            size_t go = (size_t)(k0 + krow) * N + bx * 128 + nseg * 8;
            *(uint4*)&sBh[krow * PADN + nseg * 8] = *(const uint4*)(Bh + go);
            *(uint4*)&sBl[krow * PADN + nseg * 8] = *(const uint4*)(Bl + go);
        }
        __syncthreads();

#pragma unroll
        for (int s = 0; s < 2; s++) {
            const int kk = s * 16;
            unsigned ah[4][4], al[4][4], bh[4][2], bl[4][2];
#pragma unroll
            for (int mt = 0; mt < 4; mt++) {
                int r = wm * 64 + mt * 16 + l15;
                ldsm_x4(ah[mt], &sAh[r * PADK + kk + lhi * 8]);
                ldsm_x4(al[mt], &sAl[r * PADK + kk + lhi * 8]);
            }
#pragma unroll
            for (int nt = 0; nt < 4; nt++) {
                int n0 = wn * 32 + nt * 8;
                ldsm_x2t(bh[nt], &sBh[(kk + l15) * PADN + n0]);
                ldsm_x2t(bl[nt], &sBl[(kk + l15) * PADN + n0]);
            }
#pragma unroll
            for (int mt = 0; mt < 4; mt++)
#pragma unroll
                for (int nt = 0; nt < 4; nt++) {
                    mma16816(acc[mt][nt], ah[mt], bh[nt]);
                    mma16816(acc[mt][nt], ah[mt], bl[nt]);
                    mma16816(acc[mt][nt], al[mt], bh[nt]);
                }
        }
        __syncthreads();
    }

#pragma unroll
    for (int mt = 0; mt < 4; mt++) {
        int r0 = by * 128 + wm * 64 + mt * 16 + g;
#pragma unroll
        for (int nt = 0; nt < 4; nt++) {
            int c = bx * 128 + wn * 32 + nt * 8 + tig * 2;
            float b0 = bias[c], b1 = bias[c + 1];
            float v0 = acc[mt][nt][0] + b0, v1 = acc[mt][nt][1] + b1;
            float v2 = acc[mt][nt][2] + b0, v3 = acc[mt][nt][3] + b1;
            if (relu) {
                v0 = fmaxf(v0, 0.f); v1 = fmaxf(v1, 0.f);
                v2 = fmaxf(v2, 0.f); v3 = fmaxf(v3, 0.f);
            }
            if (C) {
                *(float2*)(C + (size_t)r0 * N + c)       = make_float2(v0, v1);
                *(float2*)(C + (size_t)(r0 + 8) * N + c) = make_float2(v2, v3);
            }
            if (Ch) {
                split2_store(Ch, Cl, (size_t)r0 * N + c,       v0, v1);
                split2_store(Ch, Cl, (size_t)(r0 + 8) * N + c, v2, v3);
            }
        }
    }
}

// ---------------------------------------------------------------------------
// RoPE angle table (double precision)
// ---------------------------------------------------------------------------
__global__ void rope_table_kernel()
{
    int idx = blockIdx.x * blockDim.x + threadIdx.x;   // 32768
    int s = idx >> 5, i = idx & 31;
    double inv = exp(-((double)(2 * i) / 64.0) * log(10000.0));
    double a   = (double)s * inv;
    g_sin[idx] = (float)sin(a);
    g_cos[idx] = (float)cos(a);
}

// ---------------------------------------------------------------------------
// RoPE + split to per-head bf16 hi/lo Q/K/V ([b][h][s][d] layout).
// ---------------------------------------------------------------------------
__global__ void __launch_bounds__(256)
rope_split(const float* __restrict__ qkv,
           __nv_bfloat16* __restrict__ Qh, __nv_bfloat16* __restrict__ Ql,
           __nv_bfloat16* __restrict__ Kh, __nv_bfloat16* __restrict__ Kl,
           __nv_bfloat16* __restrict__ Vh, __nv_bfloat16* __restrict__ Vl)
{
    const int token = blockIdx.x;
    const int s = token & (Sn - 1);
    const int b = token >> 10;
    const int t = threadIdx.x;
    const int h = t >> 5;
    const int i = t & 31;
    const float sn = g_sin[s * 32 + i];
    const float cs = g_cos[s * 32 + i];
    const size_t dst = (((size_t)b * Hn + h) * Sn + s) * HDn;

    {
        const float* base = qkv + (size_t)token * (3 * Dn) + h * HDn;
        float x1 = base[i], x2 = base[i + 32];
        split_store(Qh, Ql, dst + i,      x1 * cs - x2 * sn);
        split_store(Qh, Ql, dst + i + 32, x1 * sn + x2 * cs);
    }
    {
        const float* base = qkv + (size_t)token * (3 * Dn) + Dn + h * HDn;
        float x1 = base[i], x2 = base[i + 32];
        split_store(Kh, Kl, dst + i,      x1 * cs - x2 * sn);
        split_store(Kh, Kl, dst + i + 32, x1 * sn + x2 * cs);
    }
    {
        const float* base = qkv + (size_t)token * (3 * Dn) + 2 * Dn + h * HDn;
        split_store(Vh, Vl, dst + i,      base[i]);
        split_store(Vh, Vl, dst + i + 32, base[i + 32]);
    }
}

// ---------------------------------------------------------------------------
// Flash attention on tensor cores (bf16 hi/lo split, fp32 accum).
// CTA: 64 queries x full S, 4 warps (16 q-rows each), K-tiles of 64.
// K and V both stored natural [k][d]; V frags via ldmatrix.trans.
// Output written directly as bf16 hi/lo split (feeds o-proj bgemm).
// ---------------------------------------------------------------------------
#define FPAD 72

__global__ void __launch_bounds__(128)
flash_attn_mma(const __nv_bfloat16* __restrict__ Qh, const __nv_bfloat16* __restrict__ Ql,
               const __nv_bfloat16* __restrict__ Kh, const __nv_bfloat16* __restrict__ Kl,
               const __nv_bfloat16* __restrict__ Vh, const __nv_bfloat16* __restrict__ Vl,
               __nv_bfloat16* __restrict__ Oh, __nv_bfloat16* __restrict__ Ol)
{
    __shared__ __align__(16) __nv_bfloat16 sKh[64 * FPAD], sKl[64 * FPAD];
    __shared__ __align__(16) __nv_bfloat16 sVh[64 * FPAD], sVl[64 * FPAD];

    const int t    = threadIdx.x;
    const int warp = t >> 5, lane = t & 31;
    const int g    = lane >> 2, tig = lane & 3;
    const int l15  = lane & 15, lhi = lane >> 4;
    const int qt   = blockIdx.x, h = blockIdx.y, b = blockIdx.z;
    const int q0   = qt * 64;
    const size_t bh = ((size_t)b * Hn + h) * ((size_t)Sn * HDn);
    const int wr   = warp * 16;

    // ---- stage Q tile into sK buffers, pull a-fragments, then release ----
    {
        const __nv_bfloat16* qgh = Qh + bh + (size_t)q0 * HDn;
        const __nv_bfloat16* qgl = Ql + bh + (size_t)q0 * HDn;
#pragma unroll
        for (int u = 0; u < 4; u++) {
            int idx = t + u * 128;           // 512 uint4
            int row = idx >> 3, seg = idx & 7;
            *(uint4*)&sKh[row * FPAD + seg * 8] = *(const uint4*)(qgh + row * HDn + seg * 8);
            *(uint4*)&sKl[row * FPAD + seg * 8] = *(const uint4*)(qgl + row * HDn + seg * 8);
        }
    }
    __syncthreads();

    unsigned qa_h[4][4], qa_l[4][4];
#pragma unroll
    for (int kk = 0; kk < 4; kk++) {
        ldsm_x4(qa_h[kk], &sKh[(wr + l15) * FPAD + kk * 16 + lhi * 8]);
        ldsm_x4(qa_l[kk], &sKl[(wr + l15) * FPAD + kk * 16 + lhi * 8]);
    }
    __syncthreads();

    float m0 = -INFINITY, m1 = -INFINITY, l0 = 0.f, l1 = 0.f;
    float oacc[8][4];
#pragma unroll
    for (int nt = 0; nt < 8; nt++)
#pragma unroll
        for (int i = 0; i < 4; i++) oacc[nt][i] = 0.f;

    for (int k0 = 0; k0 < Sn; k0 += 64) {
        // ---- load K and V tiles, both natural [k][d], vectorized ----
#pragma unroll
        for (int u = 0; u < 4; u++) {
            int idx = t + u * 128;
            int row = idx >> 3, seg = idx & 7;
            size_t go = bh + (size_t)(k0 + row) * HDn + seg * 8;
            *(uint4*)&sKh[row * FPAD + seg * 8] = *(const uint4*)(Kh + go);
            *(uint4*)&sKl[row * FPAD + seg * 8] = *(const uint4*)(Kl + go);
            *(uint4*)&sVh[row * FPAD + seg * 8] = *(const uint4*)(Vh + go);
            *(uint4*)&sVl[row * FPAD + seg * 8] = *(const uint4*)(Vl + go);
        }
        __syncthreads();

        // ---- S = Q K^T (3-term split) ----
        float sacc[8][4];
#pragma unroll
        for (int nt = 0; nt < 8; nt++)
#pragma unroll
            for (int i = 0; i < 4; i++) sacc[nt][i] = 0.f;

#pragma unroll
        for (int kk = 0; kk < 4; kk++) {
#pragma unroll
            for (int nt = 0; nt < 8; nt++) {
                unsigned bhf[2], blf[2];
                ldsm_x2(bhf, &sKh[(nt * 8 + (lane & 7)) * FPAD + kk * 16 + ((lane >> 3) & 1) * 8]);
                ldsm_x2(blf, &sKl[(nt * 8 + (lane & 7)) * FPAD + kk * 16 + ((lane >> 3) & 1) * 8]);
                mma16816(sacc[nt], qa_h[kk], bhf);
                mma16816(sacc[nt], qa_h[kk], blf);
                mma16816(sacc[nt], qa_l[kk], bhf);
            }
        }

        // ---- online softmax (rows g, g+8; 4 tig lanes share a row) ----
        float tm0 = -INFINITY, tm1 = -INFINITY;
#pragma unroll
        for (int nt = 0; nt < 8; nt++) {
            sacc[nt][0] *= 0.125f; sacc[nt][1] *= 0.125f;
            sacc[nt][2] *= 0.125f; sacc[nt][3] *= 0.125f;
            tm0 = fmaxf(tm0, fmaxf(sacc[nt][0], sacc[nt][1]));
            tm1 = fmaxf(tm1, fmaxf(sacc[nt][2], sacc[nt][3]));
        }
        tm0 = fmaxf(tm0, __shfl_xor_sync(0xffffffffu, tm0, 1));
        tm0 = fmaxf(tm0, __shfl_xor_sync(0xffffffffu, tm0, 2));
        tm1 = fmaxf(tm1, __shfl_xor_sync(0xffffffffu, tm1, 1));
        tm1 = fmaxf(tm1, __shfl_xor_sync(0xffffffffu, tm1, 2));

        float mn0 = fmaxf(m0, tm0), mn1 = fmaxf(m1, tm1);
        float a0 = __expf(m0 - mn0), a1 = __expf(m1 - mn1);
        m0 = mn0; m1 = mn1;

        float rs0 = 0.f, rs1 = 0.f;
#pragma unroll
        for (int nt = 0; nt < 8; nt++) {
            sacc[nt][0] = __expf(sacc[nt][0] - mn0);
            sacc[nt][1] = __expf(sacc[nt][1] - mn0);
            sacc[nt][2] = __expf(sacc[nt][2] - mn1);
            sacc[nt][3] = __expf(sacc[nt][3] - mn1);
            rs0 += sacc[nt][0] + sacc[nt][1];
            rs1 += sacc[nt][2] + sacc[nt][3];
        }
        rs0 += __shfl_xor_sync(0xffffffffu, rs0, 1);
        rs0 += __shfl_xor_sync(0xffffffffu, rs0, 2);
        rs1 += __shfl_xor_sync(0xffffffffu, rs1, 1);
        rs1 += __shfl_xor_sync(0xffffffffu, rs1, 2);
        l0 = l0 * a0 + rs0;
        l1 = l1 * a1 + rs1;

#pragma unroll
        for (int nt = 0; nt < 8; nt++) {
            oacc[nt][0] *= a0; oacc[nt][1] *= a0;
            oacc[nt][2] *= a1; oacc[nt][3] *= a1;
        }

        // ---- O += P V (P split hi/lo in registers; 3-term) ----
#pragma unroll
        for (int j = 0; j < 4; j++) {
            unsigned pah[4], pal[4];
#pragma unroll
            for (int q = 0; q < 4; q++) {
                int nt = 2 * j + (q >> 1);
                int c0 = (q & 1) * 2;
                float p0 = sacc[nt][c0], p1 = sacc[nt][c0 + 1];
                union { __nv_bfloat162 b2; unsigned u; } hh, ll;
                hh.b2 = __floats2bfloat162_rn(p0, p1);
                float2 hf = __bfloat1622float2(hh.b2);
                ll.b2 = __floats2bfloat162_rn(p0 - hf.x, p1 - hf.y);
                pah[q] = hh.u; pal[q] = ll.u;
            }
#pragma unroll
            for (int nt = 0; nt < 8; nt++) {
                unsigned vbh[2], vbl[2];
                ldsm_x2t(vbh, &sVh[(j * 16 + l15) * FPAD + nt * 8]);
                ldsm_x2t(vbl, &sVl[(j * 16 + l15) * FPAD + nt * 8]);
                mma16816(oacc[nt], pah, vbh);
                mma16816(oacc[nt], pah, vbl);
                mma16816(oacc[nt], pal, vbh);
            }
        }
        __syncthreads();
    }

    // ---- normalize + split-store to (B,S,H*HD) bf16 hi/lo ----
    float inv0 = 1.f / l0, inv1 = 1.f / l1;
    const int gq = q0 + wr + g;
    size_t o0 = (size_t)(b * Sn + gq) * Dn + h * HDn;
    size_t o1 = o0 + (size_t)8 * Dn;
#pragma unroll
    for (int nt = 0; nt < 8; nt++) {
        split2_store(Oh, Ol, o0 + nt * 8 + tig * 2, oacc[nt][0] * inv0, oacc[nt][1] * inv0);
        split2_store(Oh, Ol, o1 + nt * 8 + tig * 2, oacc[nt][2] * inv1, oacc[nt][3] * inv1);
    }
}

// ---------------------------------------------------------------------------
// LayerNorm(X + Y) * g + b, optional bf16 hi/lo split output
// ---------------------------------------------------------------------------
__global__ void __launch_bounds__(256)
ln_residual(const float* __restrict__ X, const float* __restrict__ Y,
            const float* __restrict__ g, const float* __restrict__ bta,
            float* __restrict__ out,
            __nv_bfloat16* __restrict__ outh, __nv_bfloat16* __restrict__ outl)
{
    __shared__ float red[8];
    const int row = blockIdx.x, t = threadIdx.x;
    const float* x = X + (size_t)row * Dn;
    const float* y = Y + (size_t)row * Dn;

    float v0 = x[t] + y[t];
    float v1 = x[t + 256] + y[t + 256];

    const int lane = t & 31, wid = t >> 5;
    float s = v0 + v1;
#pragma unroll
    for (int off = 16; off; off >>= 1) s += __shfl_xor_sync(0xffffffffu, s, off);
    if (!lane) red[wid] = s;
    __syncthreads();
    float mean = 0.f;
#pragma unroll
    for (int i = 0; i < 8; i++) mean += red[i];
    mean *= (1.f / 512.f);
    __syncthreads();

    float d0 = v0 - mean, d1 = v1 - mean;
    float ss = d0 * d0 + d1 * d1;
#pragma unroll
    for (int off = 16; off; off >>= 1) ss += __shfl_xor_sync(0xffffffffu, ss, off);
    if (!lane) red[wid] = ss;
    __syncthreads();
    float var = 0.f;
#pragma unroll
    for (int i = 0; i < 8; i++) var += red[i];
    var *= (1.f / 512.f);
    float inv = rsqrtf(var + 1e-5f);

    float r0 = d0 * inv * g[t]       + bta[t];
    float r1 = d1 * inv * g[t + 256] + bta[t + 256];
    out[(size_t)row * Dn + t]       = r0;
    out[(size_t)row * Dn + t + 256] = r1;
    if (outh) {
        split_store(outh, outl, (size_t)row * Dn + t,       r0);
        split_store(outh, outl, (size_t)row * Dn + t + 256, r1);
    }
}

// ---------------------------------------------------------------------------
// Launch sequence
// ---------------------------------------------------------------------------
static inline void conv(const float* in, __nv_bfloat16* hi, __nv_bfloat16* lo, int n)
{
    convert_split<<<n / 1024, 256>>>(in, hi, lo);
}

extern "C" void kernel_launch(void* const* d_in, const int* in_sizes, int n_in,
                              void* d_out, int out_size)
{
    const float* x      = (const float*)d_in[0];
    const float* w_in   = (const float*)d_in[1];
    const float* b_in   = (const float*)d_in[2];
    const float* w_qkv  = (const float*)d_in[3];
    const float* b_qkv  = (const float*)d_in[4];
    const float* w_out  = (const float*)d_in[5];
    const float* b_out  = (const float*)d_in[6];
    const float* w_ffn1 = (const float*)d_in[7];
    const float* b_ffn1 = (const float*)d_in[8];
    const float* w_ffn2 = (const float*)d_in[9];
    const float* b_ffn2 = (const float*)d_in[10];
    const float* g1     = (const float*)d_in[11];
    const float* bn1    = (const float*)d_in[12];
    const float* g2     = (const float*)d_in[13];
    const float* bn2    = (const float*)d_in[14];
    float* out = (float*)d_out;

    float *h, *qkv, *oprj, *h2, *f2;
    cudaGetSymbolAddress((void**)&h,    g_h);
    cudaGetSymbolAddress((void**)&qkv,  g_qkv);
    cudaGetSymbolAddress((void**)&oprj, g_oprj);
    cudaGetSymbolAddress((void**)&h2,   g_h2);
    cudaGetSymbolAddress((void**)&f2,   g_f2);

    __nv_bfloat16 *xh, *xl, *hh, *hl, *ah, *al, *h2h, *h2l, *f1h, *f1l;
    __nv_bfloat16 *w1h, *w1l, *wqh, *wql, *woh, *wol, *wf1h, *wf1l, *wf2h, *wf2l;
    __nv_bfloat16 *qhh, *qhl, *khh, *khl, *vhh, *vhl;
    cudaGetSymbolAddress((void**)&xh,  g_xh);   cudaGetSymbolAddress((void**)&xl,  g_xl);
    cudaGetSymbolAddress((void**)&hh,  g_hh);   cudaGetSymbolAddress((void**)&hl,  g_hl);
    cudaGetSymbolAddress((void**)&ah,  g_ah);   cudaGetSymbolAddress((void**)&al,  g_al);
    cudaGetSymbolAddress((void**)&h2h, g_h2h);  cudaGetSymbolAddress((void**)&h2l, g_h2l);
    cudaGetSymbolAddress((void**)&f1h, g_f1h);  cudaGetSymbolAddress((void**)&f1l, g_f1l);
    cudaGetSymbolAddress((void**)&w1h, g_w1h);  cudaGetSymbolAddress((void**)&w1l, g_w1l);
    cudaGetSymbolAddress((void**)&wqh, g_wqh);  cudaGetSymbolAddress((void**)&wql, g_wql);
    cudaGetSymbolAddress((void**)&woh, g_woh);  cudaGetSymbolAddress((void**)&wol, g_wol);
    cudaGetSymbolAddress((void**)&wf1h, g_wf1h); cudaGetSymbolAddress((void**)&wf1l, g_wf1l);
    cudaGetSymbolAddress((void**)&wf2h, g_wf2h); cudaGetSymbolAddress((void**)&wf2l, g_wf2l);
    cudaGetSymbolAddress((void**)&qhh, g_qheadh); cudaGetSymbolAddress((void**)&qhl, g_qheadl);
    cudaGetSymbolAddress((void**)&khh, g_kheadh); cudaGetSymbolAddress((void**)&khl, g_kheadl);
    cudaGetSymbolAddress((void**)&vhh, g_vheadh); cudaGetSymbolAddress((void**)&vhl, g_vheadl);

    // Split conversions (inputs only; activation splits are fused)
    conv(x,      xh,  xl,  TOK * CIN);
    conv(w_in,   w1h, w1l, CIN * Dn);
    conv(w_qkv,  wqh, wql, Dn * 3 * Dn);
    conv(w_out,  woh, wol, Dn * Dn);
    conv(w_ffn1, wf1h, wf1l, Dn * 4 * Dn);
    conv(w_ffn2, wf2h, wf2l, 4 * Dn * Dn);

    // 1. h = x @ w_in + b_in   (fp32 + split out)
    bgemm<<<dim3(4, 128), 256>>>(xh, xl, w1h, w1l, b_in, h, hh, hl, TOK, Dn, CIN, 0);
    // 2. qkv = h @ w_qkv + b_qkv   (fp32 only)
    bgemm<<<dim3(12, 128), 256>>>(hh, hl, wqh, wql, b_qkv, qkv,
                                  (__nv_bfloat16*)0, (__nv_bfloat16*)0, TOK, 3 * Dn, Dn, 0);
    // 3. RoPE + per-head split
    rope_table_kernel<<<128, 256>>>();
    rope_split<<<TOK, 256>>>(qkv, qhh, qhl, khh, khl, vhh, vhl);
    // 4. attention (split out feeds o-proj directly)
    flash_attn_mma<<<dim3(Sn / 64, Hn, Bn), 128>>>(qhh, qhl, khh, khl, vhh, vhl, ah, al);
    // 5. o @ w_out + b_out   (fp32 only)
    bgemm<<<dim3(4, 128), 256>>>(ah, al, woh, wol, b_out, oprj,
                                 (__nv_bfloat16*)0, (__nv_bfloat16*)0, TOK, Dn, Dn, 0);
    // 6. h2 = LN(h + o)   (fp32 + split out)
    ln_residual<<<TOK, 256>>>(h, oprj, g1, bn1, h2, h2h, h2l);
    // 7. f1 = relu(h2 @ w_ffn1 + b_ffn1)   (split only)
    bgemm<<<dim3(16, 128), 256>>>(h2h, h2l, wf1h, wf1l, b_ffn1, (float*)0,
                                  f1h, f1l, TOK, 4 * Dn, Dn, 1);
    // 8. f2 = f1 @ w_ffn2 + b_ffn2   (fp32 only)
    bgemm<<<dim3(4, 128), 256>>>(f1h, f1l, wf2h, wf2l, b_ffn2, f2,
                                 (__nv_bfloat16*)0, (__nv_bfloat16*)0, TOK, Dn, 4 * Dn, 0);
    // 9. out = LN(h2 + f2)
    ln_residual<<<TOK, 256>>>(h2, f2, g2, bn2, out, (__nv_bfloat16*)0, (__nv_bfloat16*)0);
}

// round 14
// speedup vs baseline: 4.7149x; 1.1201x over previous
#include <cuda_runtime.h>
#include <cuda_bf16.h>
#include <math.h>

// Problem shape constants
#define Bn   16
#define Sn   1024
#define CIN  1280
#define Dn   512
#define Hn   8
#define HDn  64
#define TOK  (Bn*Sn)   // 16384

// ---------------------------------------------------------------------------
// Static scratch (no cudaMalloc allowed)
// ---------------------------------------------------------------------------
__device__ float g_h   [TOK * Dn];
__device__ float g_qkv [TOK * 3 * Dn];
__device__ float g_oprj[TOK * Dn];
__device__ float g_h2  [TOK * Dn];
__device__ float g_f2  [TOK * Dn];
__device__ float g_sin [Sn * 32];
__device__ float g_cos [Sn * 32];

// bf16 hi/lo split buffers (activations + weights)
__device__ __nv_bfloat16 g_xh  [TOK * CIN],    g_xl  [TOK * CIN];
__device__ __nv_bfloat16 g_hh  [TOK * Dn],     g_hl  [TOK * Dn];
__device__ __nv_bfloat16 g_ah  [TOK * Dn],     g_al  [TOK * Dn];
__device__ __nv_bfloat16 g_h2h [TOK * Dn],     g_h2l [TOK * Dn];
__device__ __nv_bfloat16 g_f1h [TOK * 4 * Dn], g_f1l [TOK * 4 * Dn];
__device__ __nv_bfloat16 g_w1h [CIN * Dn],     g_w1l [CIN * Dn];
__device__ __nv_bfloat16 g_wqh [Dn * 3 * Dn],  g_wql [Dn * 3 * Dn];
__device__ __nv_bfloat16 g_woh [Dn * Dn],      g_wol [Dn * Dn];
__device__ __nv_bfloat16 g_wf1h[Dn * 4 * Dn],  g_wf1l[Dn * 4 * Dn];
__device__ __nv_bfloat16 g_wf2h[4 * Dn * Dn],  g_wf2l[4 * Dn * Dn];

// per-head bf16 hi/lo Q/K/V (RoPE applied), layout [b][h][s][d]
__device__ __nv_bfloat16 g_qheadh[TOK * Dn], g_qheadl[TOK * Dn];
__device__ __nv_bfloat16 g_kheadh[TOK * Dn], g_kheadl[TOK * Dn];
__device__ __nv_bfloat16 g_vheadh[TOK * Dn], g_vheadl[TOK * Dn];

// ---------------------------------------------------------------------------
// helpers
// ---------------------------------------------------------------------------
__device__ __forceinline__ void mma16816(float* d, const unsigned* a, const unsigned* b)
{
    asm volatile(
        "mma.sync.aligned.m16n8k16.row.col.f32.bf16.bf16.f32 "
        "{%0,%1,%2,%3},{%4,%5,%6,%7},{%8,%9},{%0,%1,%2,%3};"
        : "+f"(d[0]), "+f"(d[1]), "+f"(d[2]), "+f"(d[3])
        : "r"(a[0]), "r"(a[1]), "r"(a[2]), "r"(a[3]), "r"(b[0]), "r"(b[1]));
}

__device__ __forceinline__ void ldsm_x4(unsigned* r, const void* p)
{
    unsigned a = (unsigned)__cvta_generic_to_shared(p);
    asm volatile("ldmatrix.sync.aligned.m8n8.x4.shared.b16 {%0,%1,%2,%3}, [%4];"
                 : "=r"(r[0]), "=r"(r[1]), "=r"(r[2]), "=r"(r[3]) : "r"(a));
}
__device__ __forceinline__ void ldsm_x2(unsigned* r, const void* p)
{
    unsigned a = (unsigned)__cvta_generic_to_shared(p);
    asm volatile("ldmatrix.sync.aligned.m8n8.x2.shared.b16 {%0,%1}, [%2];"
                 : "=r"(r[0]), "=r"(r[1]) : "r"(a));
}
__device__ __forceinline__ void ldsm_x2t(unsigned* r, const void* p)
{
    unsigned a = (unsigned)__cvta_generic_to_shared(p);
    asm volatile("ldmatrix.sync.aligned.m8n8.x2.trans.shared.b16 {%0,%1}, [%2];"
                 : "=r"(r[0]), "=r"(r[1]) : "r"(a));
}

__device__ __forceinline__ void cp16(void* dst, const void* src)
{
    unsigned d = (unsigned)__cvta_generic_to_shared(dst);
    asm volatile("cp.async.cg.shared.global [%0], [%1], 16;" :: "r"(d), "l"(src));
}
#define CP_COMMIT() asm volatile("cp.async.commit_group;")
#define CP_WAIT(n)  asm volatile("cp.async.wait_group %0;" :: "n"(n))

__device__ __forceinline__ void split_store(__nv_bfloat16* hi, __nv_bfloat16* lo,
                                            size_t idx, float v)
{
    __nv_bfloat16 h = __float2bfloat16_rn(v);
    hi[idx] = h;
    lo[idx] = __float2bfloat16_rn(v - __bfloat162float(h));
}

__device__ __forceinline__ void split2_store(__nv_bfloat16* H, __nv_bfloat16* L,
                                             size_t off, float v0, float v1)
{
    __nv_bfloat162 hh = __floats2bfloat162_rn(v0, v1);
    float2 hf = __bfloat1622float2(hh);
    __nv_bfloat162 ll = __floats2bfloat162_rn(v0 - hf.x, v1 - hf.y);
    *(__nv_bfloat162*)(H + off) = hh;
    *(__nv_bfloat162*)(L + off) = ll;
}

// ---------------------------------------------------------------------------
// fp32 -> bf16 hi/lo split conversion (4 elements / thread)
// ---------------------------------------------------------------------------
__global__ void __launch_bounds__(256)
convert_split(const float* __restrict__ in, __nv_bfloat16* __restrict__ hi,
              __nv_bfloat16* __restrict__ lo)
{
    int idx = (blockIdx.x * 256 + threadIdx.x) * 4;
    float4 v = *(const float4*)(in + idx);
    split2_store(hi, lo, idx,     v.x, v.y);
    split2_store(hi, lo, idx + 2, v.z, v.w);
}

// ---------------------------------------------------------------------------
// Tensor-core GEMM, bf16 2-term split, 2-stage cp.async pipeline.
// 128x128 CTA tile, BK=32, 256 threads (8 warps 2x4), warp tile 64x32.
// Dynamic smem: 2 stages x (Ah|Al 128xPADK + Bh|Bl 32xPADN).
// ---------------------------------------------------------------------------
#define PADK 40
#define PADN 136
#define BG_STAGE (2 * 128 * PADK + 2 * 32 * PADN)   // 18944 bf16 elems

__device__ __forceinline__ void bg_load(__nv_bfloat16* base,
    const __nv_bfloat16* Ah, const __nv_bfloat16* Al,
    const __nv_bfloat16* Bh, const __nv_bfloat16* Bl,
    int t, int by, int bx, int k0, int N, int K)
{
    __nv_bfloat16* sAh = base;
    __nv_bfloat16* sAl = sAh + 128 * PADK;
    __nv_bfloat16* sBh = sAl + 128 * PADK;
    __nv_bfloat16* sBl = sBh + 32 * PADN;
#pragma unroll
    for (int u = 0; u < 2; u++) {
        int idx = t + u * 256;
        int row = idx >> 2, seg = idx & 3;
        size_t go = (size_t)(by * 128 + row) * K + k0 + seg * 8;
        cp16(&sAh[row * PADK + seg * 8], Ah + go);
        cp16(&sAl[row * PADK + seg * 8], Al + go);
    }
#pragma unroll
    for (int u = 0; u < 2; u++) {
        int idx  = t + u * 256;
        int krow = idx >> 4, nseg = idx & 15;
        size_t go = (size_t)(k0 + krow) * N + bx * 128 + nseg * 8;
        cp16(&sBh[krow * PADN + nseg * 8], Bh + go);
        cp16(&sBl[krow * PADN + nseg * 8], Bl + go);
    }
}

__global__ void __launch_bounds__(256)
bgemm(const __nv_bfloat16* __restrict__ Ah, const __nv_bfloat16* __restrict__ Al,
      const __nv_bfloat16* __restrict__ Bh, const __nv_bfloat16* __restrict__ Bl,
      const float* __restrict__ bias, float* __restrict__ C,
      __nv_bfloat16* __restrict__ Ch, __nv_bfloat16* __restrict__ Cl,
      int M, int N, int K, int relu)
{
    extern __shared__ __align__(16) __nv_bfloat16 dsm[];

    const int t    = threadIdx.x;
    const int warp = t >> 5, lane = t & 31;
    const int wm   = warp & 1;
    const int wn   = warp >> 1;
    const int g    = lane >> 2;
    const int tig  = lane & 3;
    const int bx   = blockIdx.x, by = blockIdx.y;
    const int l15  = lane & 15;
    const int lhi  = lane >> 4;
    const int NT   = K >> 5;

    float acc[4][4][4];
#pragma unroll
    for (int mt = 0; mt < 4; mt++)
#pragma unroll
        for (int nt = 0; nt < 4; nt++)
#pragma unroll
            for (int i = 0; i < 4; i++) acc[mt][nt][i] = 0.f;

    // prologue: stage 0
    bg_load(dsm, Ah, Al, Bh, Bl, t, by, bx, 0, N, K);
    CP_COMMIT();

    for (int it = 0; it < NT; it++) {
        if (it + 1 < NT) {
            bg_load(dsm + ((it + 1) & 1) * BG_STAGE, Ah, Al, Bh, Bl,
                    t, by, bx, (it + 1) * 32, N, K);
            CP_COMMIT();
            CP_WAIT(1);
        } else {
            CP_WAIT(0);
        }
        __syncthreads();

        __nv_bfloat16* cAh = dsm + (it & 1) * BG_STAGE;
        __nv_bfloat16* cAl = cAh + 128 * PADK;
        __nv_bfloat16* cBh = cAl + 128 * PADK;
        __nv_bfloat16* cBl = cBh + 32 * PADN;

#pragma unroll
        for (int s = 0; s < 2; s++) {
            const int kk = s * 16;
            unsigned ah[4][4], al[4][4], bh[4][2], bl[4][2];
#pragma unroll
            for (int mt = 0; mt < 4; mt++) {
                int r = wm * 64 + mt * 16 + l15;
                ldsm_x4(ah[mt], &cAh[r * PADK + kk + lhi * 8]);
                ldsm_x4(al[mt], &cAl[r * PADK + kk + lhi * 8]);
            }
#pragma unroll
            for (int nt = 0; nt < 4; nt++) {
                int n0 = wn * 32 + nt * 8;
                ldsm_x2t(bh[nt], &cBh[(kk + l15) * PADN + n0]);
                ldsm_x2t(bl[nt], &cBl[(kk + l15) * PADN + n0]);
            }
#pragma unroll
            for (int mt = 0; mt < 4; mt++)
#pragma unroll
                for (int nt = 0; nt < 4; nt++) {
                    mma16816(acc[mt][nt], ah[mt], bh[nt]);
                    mma16816(acc[mt][nt], ah[mt], bl[nt]);
                    mma16816(acc[mt][nt], al[mt], bh[nt]);
                }
        }
        __syncthreads();
    }

#pragma unroll
    for (int mt = 0; mt < 4; mt++) {
        int r0 = by * 128 + wm * 64 + mt * 16 + g;
#pragma unroll
        for (int nt = 0; nt < 4; nt++) {
            int c = bx * 128 + wn * 32 + nt * 8 + tig * 2;
            float b0 = bias[c], b1 = bias[c + 1];
            float v0 = acc[mt][nt][0] + b0, v1 = acc[mt][nt][1] + b1;
            float v2 = acc[mt][nt][2] + b0, v3 = acc[mt][nt][3] + b1;
            if (relu) {
                v0 = fmaxf(v0, 0.f); v1 = fmaxf(v1, 0.f);
                v2 = fmaxf(v2, 0.f); v3 = fmaxf(v3, 0.f);
            }
            if (C) {
                *(float2*)(C + (size_t)r0 * N + c)       = make_float2(v0, v1);
                *(float2*)(C + (size_t)(r0 + 8) * N + c) = make_float2(v2, v3);
            }
            if (Ch) {
                split2_store(Ch, Cl, (size_t)r0 * N + c,       v0, v1);
                split2_store(Ch, Cl, (size_t)(r0 + 8) * N + c, v2, v3);
            }
        }
    }
}

// ---------------------------------------------------------------------------
// RoPE angle table (double precision)
// ---------------------------------------------------------------------------
__global__ void rope_table_kernel()
{
    int idx = blockIdx.x * blockDim.x + threadIdx.x;   // 32768
    int s = idx >> 5, i = idx & 31;
    double inv = exp(-((double)(2 * i) / 64.0) * log(10000.0));
    double a   = (double)s * inv;
    g_sin[idx] = (float)sin(a);
    g_cos[idx] = (float)cos(a);
}

// ---------------------------------------------------------------------------
// RoPE + split to per-head bf16 hi/lo Q/K/V ([b][h][s][d] layout).
// ---------------------------------------------------------------------------
__global__ void __launch_bounds__(256)
rope_split(const float* __restrict__ qkv,
           __nv_bfloat16* __restrict__ Qh, __nv_bfloat16* __restrict__ Ql,
           __nv_bfloat16* __restrict__ Kh, __nv_bfloat16* __restrict__ Kl,
           __nv_bfloat16* __restrict__ Vh, __nv_bfloat16* __restrict__ Vl)
{
    const int token = blockIdx.x;
    const int s = token & (Sn - 1);
    const int b = token >> 10;
    const int t = threadIdx.x;
    const int h = t >> 5;
    const int i = t & 31;
    const float sn = g_sin[s * 32 + i];
    const float cs = g_cos[s * 32 + i];
    const size_t dst = (((size_t)b * Hn + h) * Sn + s) * HDn;

    {
        const float* base = qkv + (size_t)token * (3 * Dn) + h * HDn;
        float x1 = base[i], x2 = base[i + 32];
        split_store(Qh, Ql, dst + i,      x1 * cs - x2 * sn);
        split_store(Qh, Ql, dst + i + 32, x1 * sn + x2 * cs);
    }
    {
        const float* base = qkv + (size_t)token * (3 * Dn) + Dn + h * HDn;
        float x1 = base[i], x2 = base[i + 32];
        split_store(Kh, Kl, dst + i,      x1 * cs - x2 * sn);
        split_store(Kh, Kl, dst + i + 32, x1 * sn + x2 * cs);
    }
    {
        const float* base = qkv + (size_t)token * (3 * Dn) + 2 * Dn + h * HDn;
        split_store(Vh, Vl, dst + i,      base[i]);
        split_store(Vh, Vl, dst + i + 32, base[i + 32]);
    }
}

// ---------------------------------------------------------------------------
// Flash attention on tensor cores, 2-stage cp.async K/V pipeline.
// CTA: 64 queries x full S, 4 warps (16 q-rows each), K-tiles of 64.
// Dynamic smem: 2 stages x (Kh|Kl|Vh|Vl, each 64xFPAD).
// ---------------------------------------------------------------------------
#define FPAD 72
#define FL_STAGE (4 * 64 * FPAD)   // 18432 bf16 elems

__device__ __forceinline__ void fl_load(__nv_bfloat16* base,
    const __nv_bfloat16* Kh, const __nv_bfloat16* Kl,
    const __nv_bfloat16* Vh, const __nv_bfloat16* Vl,
    int t, size_t bh, int k0)
{
    __nv_bfloat16* bKh = base;
    __nv_bfloat16* bKl = bKh + 64 * FPAD;
    __nv_bfloat16* bVh = bKl + 64 * FPAD;
    __nv_bfloat16* bVl = bVh + 64 * FPAD;
#pragma unroll
    for (int u = 0; u < 4; u++) {
        int idx = t + u * 128;
        int row = idx >> 3, seg = idx & 7;
        size_t go = bh + (size_t)(k0 + row) * HDn + seg * 8;
        cp16(&bKh[row * FPAD + seg * 8], Kh + go);
        cp16(&bKl[row * FPAD + seg * 8], Kl + go);
        cp16(&bVh[row * FPAD + seg * 8], Vh + go);
        cp16(&bVl[row * FPAD + seg * 8], Vl + go);
    }
}

__global__ void __launch_bounds__(128)
flash_attn_mma(const __nv_bfloat16* __restrict__ Qh, const __nv_bfloat16* __restrict__ Ql,
               const __nv_bfloat16* __restrict__ Kh, const __nv_bfloat16* __restrict__ Kl,
               const __nv_bfloat16* __restrict__ Vh, const __nv_bfloat16* __restrict__ Vl,
               __nv_bfloat16* __restrict__ Oh, __nv_bfloat16* __restrict__ Ol)
{
    extern __shared__ __align__(16) __nv_bfloat16 fsm[];

    const int t    = threadIdx.x;
    const int warp = t >> 5, lane = t & 31;
    const int g    = lane >> 2, tig = lane & 3;
    const int l15  = lane & 15, lhi = lane >> 4;
    const int qt   = blockIdx.x, h = blockIdx.y, b = blockIdx.z;
    const int q0   = qt * 64;
    const size_t bh = ((size_t)b * Hn + h) * ((size_t)Sn * HDn);
    const int wr   = warp * 16;

    // ---- stage Q tile into stage-0 K buffers, pull a-fragments ----
    {
        __nv_bfloat16* sQh = fsm;
        __nv_bfloat16* sQl = fsm + 64 * FPAD;
        const __nv_bfloat16* qgh = Qh + bh + (size_t)q0 * HDn;
        const __nv_bfloat16* qgl = Ql + bh + (size_t)q0 * HDn;
#pragma unroll
        for (int u = 0; u < 4; u++) {
            int idx = t + u * 128;
            int row = idx >> 3, seg = idx & 7;
            *(uint4*)&sQh[row * FPAD + seg * 8] = *(const uint4*)(qgh + row * HDn + seg * 8);
            *(uint4*)&sQl[row * FPAD + seg * 8] = *(const uint4*)(qgl + row * HDn + seg * 8);
        }
    }
    __syncthreads();

    unsigned qa_h[4][4], qa_l[4][4];
#pragma unroll
    for (int kk = 0; kk < 4; kk++) {
        ldsm_x4(qa_h[kk], &fsm[(wr + l15) * FPAD + kk * 16 + lhi * 8]);
        ldsm_x4(qa_l[kk], &fsm[64 * FPAD + (wr + l15) * FPAD + kk * 16 + lhi * 8]);
    }
    __syncthreads();

    float m0 = -INFINITY, m1 = -INFINITY, l0 = 0.f, l1 = 0.f;
    float oacc[8][4];
#pragma unroll
    for (int nt = 0; nt < 8; nt++)
#pragma unroll
        for (int i = 0; i < 4; i++) oacc[nt][i] = 0.f;

    // prologue: stage 0 <- tile 0
    fl_load(fsm, Kh, Kl, Vh, Vl, t, bh, 0);
    CP_COMMIT();

    for (int it = 0; it < Sn / 64; it++) {
        if (it + 1 < Sn / 64) {
            fl_load(fsm + ((it + 1) & 1) * FL_STAGE, Kh, Kl, Vh, Vl,
                    t, bh, (it + 1) * 64);
            CP_COMMIT();
            CP_WAIT(1);
        } else {
            CP_WAIT(0);
        }
        __syncthreads();

        __nv_bfloat16* bKh = fsm + (it & 1) * FL_STAGE;
        __nv_bfloat16* bKl = bKh + 64 * FPAD;
        __nv_bfloat16* bVh = bKl + 64 * FPAD;
        __nv_bfloat16* bVl = bVh + 64 * FPAD;

        // ---- S = Q K^T (3-term split) ----
        float sacc[8][4];
#pragma unroll
        for (int nt = 0; nt < 8; nt++)
#pragma unroll
            for (int i = 0; i < 4; i++) sacc[nt][i] = 0.f;

#pragma unroll
        for (int kk = 0; kk < 4; kk++) {
#pragma unroll
            for (int nt = 0; nt < 8; nt++) {
                unsigned bhf[2], blf[2];
                ldsm_x2(bhf, &bKh[(nt * 8 + (lane & 7)) * FPAD + kk * 16 + ((lane >> 3) & 1) * 8]);
                ldsm_x2(blf, &bKl[(nt * 8 + (lane & 7)) * FPAD + kk * 16 + ((lane >> 3) & 1) * 8]);
                mma16816(sacc[nt], qa_h[kk], bhf);
                mma16816(sacc[nt], qa_h[kk], blf);
                mma16816(sacc[nt], qa_l[kk], bhf);
            }
        }

        // ---- online softmax (rows g, g+8; 4 tig lanes share a row) ----
        float tm0 = -INFINITY, tm1 = -INFINITY;
#pragma unroll
        for (int nt = 0; nt < 8; nt++) {
            sacc[nt][0] *= 0.125f; sacc[nt][1] *= 0.125f;
            sacc[nt][2] *= 0.125f; sacc[nt][3] *= 0.125f;
            tm0 = fmaxf(tm0, fmaxf(sacc[nt][0], sacc[nt][1]));
            tm1 = fmaxf(tm1, fmaxf(sacc[nt][2], sacc[nt][3]));
        }
        tm0 = fmaxf(tm0, __shfl_xor_sync(0xffffffffu, tm0, 1));
        tm0 = fmaxf(tm0, __shfl_xor_sync(0xffffffffu, tm0, 2));
        tm1 = fmaxf(tm1, __shfl_xor_sync(0xffffffffu, tm1, 1));
        tm1 = fmaxf(tm1, __shfl_xor_sync(0xffffffffu, tm1, 2));

        float mn0 = fmaxf(m0, tm0), mn1 = fmaxf(m1, tm1);
        float a0 = __expf(m0 - mn0), a1 = __expf(m1 - mn1);
        m0 = mn0; m1 = mn1;

        float rs0 = 0.f, rs1 = 0.f;
#pragma unroll
        for (int nt = 0; nt < 8; nt++) {
            sacc[nt][0] = __expf(sacc[nt][0] - mn0);
            sacc[nt][1] = __expf(sacc[nt][1] - mn0);
            sacc[nt][2] = __expf(sacc[nt][2] - mn1);
            sacc[nt][3] = __expf(sacc[nt][3] - mn1);
            rs0 += sacc[nt][0] + sacc[nt][1];
            rs1 += sacc[nt][2] + sacc[nt][3];
        }
        rs0 += __shfl_xor_sync(0xffffffffu, rs0, 1);
        rs0 += __shfl_xor_sync(0xffffffffu, rs0, 2);
        rs1 += __shfl_xor_sync(0xffffffffu, rs1, 1);
        rs1 += __shfl_xor_sync(0xffffffffu, rs1, 2);
        l0 = l0 * a0 + rs0;
        l1 = l1 * a1 + rs1;

#pragma unroll
        for (int nt = 0; nt < 8; nt++) {
            oacc[nt][0] *= a0; oacc[nt][1] *= a0;
            oacc[nt][2] *= a1; oacc[nt][3] *= a1;
        }

        // ---- O += P V (P split hi/lo in registers; 3-term) ----
#pragma unroll
        for (int j = 0; j < 4; j++) {
            unsigned pah[4], pal[4];
#pragma unroll
            for (int q = 0; q < 4; q++) {
                int nt = 2 * j + (q >> 1);
                int c0 = (q & 1) * 2;
                float p0 = sacc[nt][c0], p1 = sacc[nt][c0 + 1];
                union { __nv_bfloat162 b2; unsigned u; } hh, ll;
                hh.b2 = __floats2bfloat162_rn(p0, p1);
                float2 hf = __bfloat1622float2(hh.b2);
                ll.b2 = __floats2bfloat162_rn(p0 - hf.x, p1 - hf.y);
                pah[q] = hh.u; pal[q] = ll.u;
            }
#pragma unroll
            for (int nt = 0; nt < 8; nt++) {
                unsigned vbh[2], vbl[2];
                ldsm_x2t(vbh, &bVh[(j * 16 + l15) * FPAD + nt * 8]);
                ldsm_x2t(vbl, &bVl[(j * 16 + l15) * FPAD + nt * 8]);
                mma16816(oacc[nt], pah, vbh);
                mma16816(oacc[nt], pah, vbl);
                mma16816(oacc[nt], pal, vbh);
            }
        }
        __syncthreads();
    }

    // ---- normalize + split-store to (B,S,H*HD) bf16 hi/lo ----
    float inv0 = 1.f / l0, inv1 = 1.f / l1;
    const int gq = q0 + wr + g;
    size_t o0 = (size_t)(b * Sn + gq) * Dn + h * HDn;
    size_t o1 = o0 + (size_t)8 * Dn;
#pragma unroll
    for (int nt = 0; nt < 8; nt++) {
        split2_store(Oh, Ol, o0 + nt * 8 + tig * 2, oacc[nt][0] * inv0, oacc[nt][1] * inv0);
        split2_store(Oh, Ol, o1 + nt * 8 + tig * 2, oacc[nt][2] * inv1, oacc[nt][3] * inv1);
    }
}

// ---------------------------------------------------------------------------
// LayerNorm(X + Y) * g + b, optional bf16 hi/lo split output
// ---------------------------------------------------------------------------
__global__ void __launch_bounds__(256)
ln_residual(const float* __restrict__ X, const float* __restrict__ Y,
            const float* __restrict__ g, const float* __restrict__ bta,
            float* __restrict__ out,
            __nv_bfloat16* __restrict__ outh, __nv_bfloat16* __restrict__ outl)
{
    __shared__ float red[8];
    const int row = blockIdx.x, t = threadIdx.x;
    const float* x = X + (size_t)row * Dn;
    const float* y = Y + (size_t)row * Dn;

    float v0 = x[t] + y[t];
    float v1 = x[t + 256] + y[t + 256];

    const int lane = t & 31, wid = t >> 5;
    float s = v0 + v1;
#pragma unroll
    for (int off = 16; off; off >>= 1) s += __shfl_xor_sync(0xffffffffu, s, off);
    if (!lane) red[wid] = s;
    __syncthreads();
    float mean = 0.f;
#pragma unroll
    for (int i = 0; i < 8; i++) mean += red[i];
    mean *= (1.f / 512.f);
    __syncthreads();

    float d0 = v0 - mean, d1 = v1 - mean;
    float ss = d0 * d0 + d1 * d1;
#pragma unroll
    for (int off = 16; off; off >>= 1) ss += __shfl_xor_sync(0xffffffffu, ss, off);
    if (!lane) red[wid] = ss;
    __syncthreads();
    float var = 0.f;
#pragma unroll
    for (int i = 0; i < 8; i++) var += red[i];
    var *= (1.f / 512.f);
    float inv = rsqrtf(var + 1e-5f);

    float r0 = d0 * inv * g[t]       + bta[t];
    float r1 = d1 * inv * g[t + 256] + bta[t + 256];
    out[(size_t)row * Dn + t]       = r0;
    out[(size_t)row * Dn + t + 256] = r1;
    if (outh) {
        split_store(outh, outl, (size_t)row * Dn + t,       r0);
        split_store(outh, outl, (size_t)row * Dn + t + 256, r1);
    }
}

// ---------------------------------------------------------------------------
// Launch sequence
// ---------------------------------------------------------------------------
static inline void conv(const float* in, __nv_bfloat16* hi, __nv_bfloat16* lo, int n)
{
    convert_split<<<n / 1024, 256>>>(in, hi, lo);
}

extern "C" void kernel_launch(void* const* d_in, const int* in_sizes, int n_in,
                              void* d_out, int out_size)
{
    const float* x      = (const float*)d_in[0];
    const float* w_in   = (const float*)d_in[1];
    const float* b_in   = (const float*)d_in[2];
    const float* w_qkv  = (const float*)d_in[3];
    const float* b_qkv  = (const float*)d_in[4];
    const float* w_out  = (const float*)d_in[5];
    const float* b_out  = (const float*)d_in[6];
    const float* w_ffn1 = (const float*)d_in[7];
    const float* b_ffn1 = (const float*)d_in[8];
    const float* w_ffn2 = (const float*)d_in[9];
    const float* b_ffn2 = (const float*)d_in[10];
    const float* g1     = (const float*)d_in[11];
    const float* bn1    = (const float*)d_in[12];
    const float* g2     = (const float*)d_in[13];
    const float* bn2    = (const float*)d_in[14];
    float* out = (float*)d_out;

    const int BG_SMEM = 2 * BG_STAGE * (int)sizeof(__nv_bfloat16);   // 75776
    const int FL_SMEM = 2 * FL_STAGE * (int)sizeof(__nv_bfloat16);   // 73728
    cudaFuncSetAttribute(bgemm, cudaFuncAttributeMaxDynamicSharedMemorySize, BG_SMEM);
    cudaFuncSetAttribute(flash_attn_mma, cudaFuncAttributeMaxDynamicSharedMemorySize, FL_SMEM);

    float *h, *qkv, *oprj, *h2, *f2;
    cudaGetSymbolAddress((void**)&h,    g_h);
    cudaGetSymbolAddress((void**)&qkv,  g_qkv);
    cudaGetSymbolAddress((void**)&oprj, g_oprj);
    cudaGetSymbolAddress((void**)&h2,   g_h2);
    cudaGetSymbolAddress((void**)&f2,   g_f2);

    __nv_bfloat16 *xh, *xl, *hh, *hl, *ah, *al, *h2h, *h2l, *f1h, *f1l;
    __nv_bfloat16 *w1h, *w1l, *wqh, *wql, *woh, *wol, *wf1h, *wf1l, *wf2h, *wf2l;
    __nv_bfloat16 *qhh, *qhl, *khh, *khl, *vhh, *vhl;
    cudaGetSymbolAddress((void**)&xh,  g_xh);   cudaGetSymbolAddress((void**)&xl,  g_xl);
    cudaGetSymbolAddress((void**)&hh,  g_hh);   cudaGetSymbolAddress((void**)&hl,  g_hl);
    cudaGetSymbolAddress((void**)&ah,  g_ah);   cudaGetSymbolAddress((void**)&al,  g_al);
    cudaGetSymbolAddress((void**)&h2h, g_h2h);  cudaGetSymbolAddress((void**)&h2l, g_h2l);
    cudaGetSymbolAddress((void**)&f1h, g_f1h);  cudaGetSymbolAddress((void**)&f1l, g_f1l);
    cudaGetSymbolAddress((void**)&w1h, g_w1h);  cudaGetSymbolAddress((void**)&w1l, g_w1l);
    cudaGetSymbolAddress((void**)&wqh, g_wqh);  cudaGetSymbolAddress((void**)&wql, g_wql);
    cudaGetSymbolAddress((void**)&woh, g_woh);  cudaGetSymbolAddress((void**)&wol, g_wol);
    cudaGetSymbolAddress((void**)&wf1h, g_wf1h); cudaGetSymbolAddress((void**)&wf1l, g_wf1l);
    cudaGetSymbolAddress((void**)&wf2h, g_wf2h); cudaGetSymbolAddress((void**)&wf2l, g_wf2l);
    cudaGetSymbolAddress((void**)&qhh, g_qheadh); cudaGetSymbolAddress((void**)&qhl, g_qheadl);
    cudaGetSymbolAddress((void**)&khh, g_kheadh); cudaGetSymbolAddress((void**)&khl, g_kheadl);
    cudaGetSymbolAddress((void**)&vhh, g_vheadh); cudaGetSymbolAddress((void**)&vhl, g_vheadl);

    // Split conversions (inputs only; activation splits are fused)
    conv(x,      xh,  xl,  TOK * CIN);
    conv(w_in,   w1h, w1l, CIN * Dn);
    conv(w_qkv,  wqh, wql, Dn * 3 * Dn);
    conv(w_out,  woh, wol, Dn * Dn);
    conv(w_ffn1, wf1h, wf1l, Dn * 4 * Dn);
    conv(w_ffn2, wf2h, wf2l, 4 * Dn * Dn);

    // 1. h = x @ w_in + b_in   (fp32 + split out)
    bgemm<<<dim3(4, 128), 256, BG_SMEM>>>(xh, xl, w1h, w1l, b_in, h, hh, hl, TOK, Dn, CIN, 0);
    // 2. qkv = h @ w_qkv + b_qkv   (fp32 only)
    bgemm<<<dim3(12, 128), 256, BG_SMEM>>>(hh, hl, wqh, wql, b_qkv, qkv,
                                  (__nv_bfloat16*)0, (__nv_bfloat16*)0, TOK, 3 * Dn, Dn, 0);
    // 3. RoPE + per-head split
    rope_table_kernel<<<128, 256>>>();
    rope_split<<<TOK, 256>>>(qkv, qhh, qhl, khh, khl, vhh, vhl);
    // 4. attention (split out feeds o-proj directly)
    flash_attn_mma<<<dim3(Sn / 64, Hn, Bn), 128, FL_SMEM>>>(qhh, qhl, khh, khl, vhh, vhl, ah, al);
    // 5. o @ w_out + b_out   (fp32 only)
    bgemm<<<dim3(4, 128), 256, BG_SMEM>>>(ah, al, woh, wol, b_out, oprj,
                                 (__nv_bfloat16*)0, (__nv_bfloat16*)0, TOK, Dn, Dn, 0);
    // 6. h2 = LN(h + o)   (fp32 + split out)
    ln_residual<<<TOK, 256>>>(h, oprj, g1, bn1, h2, h2h, h2l);
    // 7. f1 = relu(h2 @ w_ffn1 + b_ffn1)   (split only)
    bgemm<<<dim3(16, 128), 256, BG_SMEM>>>(h2h, h2l, wf1h, wf1l, b_ffn1, (float*)0,
                                  f1h, f1l, TOK, 4 * Dn, Dn, 1);
    // 8. f2 = f1 @ w_ffn2 + b_ffn2   (fp32 only)
    bgemm<<<dim3(4, 128), 256, BG_SMEM>>>(f1h, f1l, wf2h, wf2l, b_ffn2, f2,
                                 (__nv_bfloat16*)0, (__nv_bfloat16*)0, TOK, Dn, 4 * Dn, 0);
    // 9. out = LN(h2 + f2)
    ln_residual<<<TOK, 256>>>(h2, f2, g2, bn2, out, (__nv_bfloat16*)0, (__nv_bfloat16*)0);
}

// round 16
// speedup vs baseline: 4.7743x; 1.0126x over previous
#include <cuda_runtime.h>
#include <cuda_bf16.h>
#include <math.h>

// Problem shape constants
#define Bn   16
#define Sn   1024
#define CIN  1280
#define Dn   512
#define Hn   8
#define HDn  64
#define TOK  (Bn*Sn)   // 16384

// ---------------------------------------------------------------------------
// Static scratch (no cudaMalloc allowed)
// ---------------------------------------------------------------------------
__device__ float g_h   [TOK * Dn];
__device__ float g_qkv [TOK * 3 * Dn];
__device__ float g_oprj[TOK * Dn];
__device__ float g_h2  [TOK * Dn];
__device__ float g_f2  [TOK * Dn];
__device__ float g_sin [Sn * 32];
__device__ float g_cos [Sn * 32];

// bf16 hi/lo split buffers (activations + weights)
__device__ __nv_bfloat16 g_xh  [TOK * CIN],    g_xl  [TOK * CIN];
__device__ __nv_bfloat16 g_hh  [TOK * Dn],     g_hl  [TOK * Dn];
__device__ __nv_bfloat16 g_ah  [TOK * Dn],     g_al  [TOK * Dn];
__device__ __nv_bfloat16 g_h2h [TOK * Dn],     g_h2l [TOK * Dn];
__device__ __nv_bfloat16 g_f1h [TOK * 4 * Dn], g_f1l [TOK * 4 * Dn];
__device__ __nv_bfloat16 g_w1h [CIN * Dn],     g_w1l [CIN * Dn];
__device__ __nv_bfloat16 g_wqh [Dn * 3 * Dn],  g_wql [Dn * 3 * Dn];
__device__ __nv_bfloat16 g_woh [Dn * Dn],      g_wol [Dn * Dn];
__device__ __nv_bfloat16 g_wf1h[Dn * 4 * Dn],  g_wf1l[Dn * 4 * Dn];
__device__ __nv_bfloat16 g_wf2h[4 * Dn * Dn],  g_wf2l[4 * Dn * Dn];

// per-head bf16 hi/lo Q/K/V (RoPE applied), layout [b][h][s][d]
__device__ __nv_bfloat16 g_qheadh[TOK * Dn], g_qheadl[TOK * Dn];
__device__ __nv_bfloat16 g_kheadh[TOK * Dn], g_kheadl[TOK * Dn];
__device__ __nv_bfloat16 g_vheadh[TOK * Dn], g_vheadl[TOK * Dn];

// ---------------------------------------------------------------------------
// helpers
// ---------------------------------------------------------------------------
__device__ __forceinline__ void mma16816(float* d, const unsigned* a, const unsigned* b)
{
    asm volatile(
        "mma.sync.aligned.m16n8k16.row.col.f32.bf16.bf16.f32 "
        "{%0,%1,%2,%3},{%4,%5,%6,%7},{%8,%9},{%0,%1,%2,%3};"
        : "+f"(d[0]), "+f"(d[1]), "+f"(d[2]), "+f"(d[3])
        : "r"(a[0]), "r"(a[1]), "r"(a[2]), "r"(a[3]), "r"(b[0]), "r"(b[1]));
}

__device__ __forceinline__ void ldsm_x4(unsigned* r, const void* p)
{
    unsigned a = (unsigned)__cvta_generic_to_shared(p);
    asm volatile("ldmatrix.sync.aligned.m8n8.x4.shared.b16 {%0,%1,%2,%3}, [%4];"
                 : "=r"(r[0]), "=r"(r[1]), "=r"(r[2]), "=r"(r[3]) : "r"(a));
}
__device__ __forceinline__ void ldsm_x2(unsigned* r, const void* p)
{
    unsigned a = (unsigned)__cvta_generic_to_shared(p);
    asm volatile("ldmatrix.sync.aligned.m8n8.x2.shared.b16 {%0,%1}, [%2];"
                 : "=r"(r[0]), "=r"(r[1]) : "r"(a));
}
__device__ __forceinline__ void ldsm_x2t(unsigned* r, const void* p)
{
    unsigned a = (unsigned)__cvta_generic_to_shared(p);
    asm volatile("ldmatrix.sync.aligned.m8n8.x2.trans.shared.b16 {%0,%1}, [%2];"
                 : "=r"(r[0]), "=r"(r[1]) : "r"(a));
}

__device__ __forceinline__ void cp16(void* dst, const void* src)
{
    unsigned d = (unsigned)__cvta_generic_to_shared(dst);
    asm volatile("cp.async.cg.shared.global [%0], [%1], 16;" :: "r"(d), "l"(src));
}
#define CP_COMMIT() asm volatile("cp.async.commit_group;")
#define CP_WAIT(n)  asm volatile("cp.async.wait_group %0;" :: "n"(n))

__device__ __forceinline__ void split_store(__nv_bfloat16* hi, __nv_bfloat16* lo,
                                            size_t idx, float v)
{
    __nv_bfloat16 h = __float2bfloat16_rn(v);
    hi[idx] = h;
    lo[idx] = __float2bfloat16_rn(v - __bfloat162float(h));
}

__device__ __forceinline__ void split2_store(__nv_bfloat16* H, __nv_bfloat16* L,
                                             size_t off, float v0, float v1)
{
    __nv_bfloat162 hh = __floats2bfloat162_rn(v0, v1);
    float2 hf = __bfloat1622float2(hh);
    __nv_bfloat162 ll = __floats2bfloat162_rn(v0 - hf.x, v1 - hf.y);
    *(__nv_bfloat162*)(H + off) = hh;
    *(__nv_bfloat162*)(L + off) = ll;
}

// ---------------------------------------------------------------------------
// fp32 -> bf16 hi/lo split conversion (4 elements / thread)
// ---------------------------------------------------------------------------
__global__ void __launch_bounds__(256)
convert_split(const float* __restrict__ in, __nv_bfloat16* __restrict__ hi,
              __nv_bfloat16* __restrict__ lo)
{
    int idx = (blockIdx.x * 256 + threadIdx.x) * 4;
    float4 v = *(const float4*)(in + idx);
    split2_store(hi, lo, idx,     v.x, v.y);
    split2_store(hi, lo, idx + 2, v.z, v.w);
}

// ---------------------------------------------------------------------------
// Tensor-core GEMM, bf16 2-term split, 2-stage cp.async pipeline.
// (unchanged from validated R14)
// ---------------------------------------------------------------------------
#define PADK 40
#define PADN 136
#define BG_STAGE (2 * 128 * PADK + 2 * 32 * PADN)   // 18944 bf16 elems

__device__ __forceinline__ void bg_load(__nv_bfloat16* base,
    const __nv_bfloat16* Ah, const __nv_bfloat16* Al,
    const __nv_bfloat16* Bh, const __nv_bfloat16* Bl,
    int t, int by, int bx, int k0, int N, int K)
{
    __nv_bfloat16* sAh = base;
    __nv_bfloat16* sAl = sAh + 128 * PADK;
    __nv_bfloat16* sBh = sAl + 128 * PADK;
    __nv_bfloat16* sBl = sBh + 32 * PADN;
#pragma unroll
    for (int u = 0; u < 2; u++) {
        int idx = t + u * 256;
        int row = idx >> 2, seg = idx & 3;
        size_t go = (size_t)(by * 128 + row) * K + k0 + seg * 8;
        cp16(&sAh[row * PADK + seg * 8], Ah + go);
        cp16(&sAl[row * PADK + seg * 8], Al + go);
    }
#pragma unroll
    for (int u = 0; u < 2; u++) {
        int idx  = t + u * 256;
        int krow = idx >> 4, nseg = idx & 15;
        size_t go = (size_t)(k0 + krow) * N + bx * 128 + nseg * 8;
        cp16(&sBh[krow * PADN + nseg * 8], Bh + go);
        cp16(&sBl[krow * PADN + nseg * 8], Bl + go);
    }
}

__global__ void __launch_bounds__(256)
bgemm(const __nv_bfloat16* __restrict__ Ah, const __nv_bfloat16* __restrict__ Al,
      const __nv_bfloat16* __restrict__ Bh, const __nv_bfloat16* __restrict__ Bl,
      const float* __restrict__ bias, float* __restrict__ C,
      __nv_bfloat16* __restrict__ Ch, __nv_bfloat16* __restrict__ Cl,
      int M, int N, int K, int relu)
{
    extern __shared__ __align__(16) __nv_bfloat16 dsm[];

    const int t    = threadIdx.x;
    const int warp = t >> 5, lane = t & 31;
    const int wm   = warp & 1;
    const int wn   = warp >> 1;
    const int g    = lane >> 2;
    const int tig  = lane & 3;
    const int bx   = blockIdx.x, by = blockIdx.y;
    const int l15  = lane & 15;
    const int lhi  = lane >> 4;
    const int NT   = K >> 5;

    float acc[4][4][4];
#pragma unroll
    for (int mt = 0; mt < 4; mt++)
#pragma unroll
        for (int nt = 0; nt < 4; nt++)
#pragma unroll
            for (int i = 0; i < 4; i++) acc[mt][nt][i] = 0.f;

    bg_load(dsm, Ah, Al, Bh, Bl, t, by, bx, 0, N, K);
    CP_COMMIT();

    for (int it = 0; it < NT; it++) {
        if (it + 1 < NT) {
            bg_load(dsm + ((it + 1) & 1) * BG_STAGE, Ah, Al, Bh, Bl,
                    t, by, bx, (it + 1) * 32, N, K);
            CP_COMMIT();
            CP_WAIT(1);
        } else {
            CP_WAIT(0);
        }
        __syncthreads();

        __nv_bfloat16* cAh = dsm + (it & 1) * BG_STAGE;
        __nv_bfloat16* cAl = cAh + 128 * PADK;
        __nv_bfloat16* cBh = cAl + 128 * PADK;
        __nv_bfloat16* cBl = cBh + 32 * PADN;

#pragma unroll
        for (int s = 0; s < 2; s++) {
            const int kk = s * 16;
            unsigned ah[4][4], al[4][4], bh[4][2], bl[4][2];
#pragma unroll
            for (int mt = 0; mt < 4; mt++) {
                int r = wm * 64 + mt * 16 + l15;
                ldsm_x4(ah[mt], &cAh[r * PADK + kk + lhi * 8]);
                ldsm_x4(al[mt], &cAl[r * PADK + kk + lhi * 8]);
            }
#pragma unroll
            for (int nt = 0; nt < 4; nt++) {
                int n0 = wn * 32 + nt * 8;
                ldsm_x2t(bh[nt], &cBh[(kk + l15) * PADN + n0]);
                ldsm_x2t(bl[nt], &cBl[(kk + l15) * PADN + n0]);
            }
#pragma unroll
            for (int mt = 0; mt < 4; mt++)
#pragma unroll
                for (int nt = 0; nt < 4; nt++) {
                    mma16816(acc[mt][nt], ah[mt], bh[nt]);
                    mma16816(acc[mt][nt], ah[mt], bl[nt]);
                    mma16816(acc[mt][nt], al[mt], bh[nt]);
                }
        }
        __syncthreads();
    }

#pragma unroll
    for (int mt = 0; mt < 4; mt++) {
        int r0 = by * 128 + wm * 64 + mt * 16 + g;
#pragma unroll
        for (int nt = 0; nt < 4; nt++) {
            int c = bx * 128 + wn * 32 + nt * 8 + tig * 2;
            float b0 = bias[c], b1 = bias[c + 1];
            float v0 = acc[mt][nt][0] + b0, v1 = acc[mt][nt][1] + b1;
            float v2 = acc[mt][nt][2] + b0, v3 = acc[mt][nt][3] + b1;
            if (relu) {
                v0 = fmaxf(v0, 0.f); v1 = fmaxf(v1, 0.f);
                v2 = fmaxf(v2, 0.f); v3 = fmaxf(v3, 0.f);
            }
            if (C) {
                *(float2*)(C + (size_t)r0 * N + c)       = make_float2(v0, v1);
                *(float2*)(C + (size_t)(r0 + 8) * N + c) = make_float2(v2, v3);
            }
            if (Ch) {
                split2_store(Ch, Cl, (size_t)r0 * N + c,       v0, v1);
                split2_store(Ch, Cl, (size_t)(r0 + 8) * N + c, v2, v3);
            }
        }
    }
}

// ---------------------------------------------------------------------------
// RoPE angle table (double precision)
// ---------------------------------------------------------------------------
__global__ void rope_table_kernel()
{
    int idx = blockIdx.x * blockDim.x + threadIdx.x;   // 32768
    int s = idx >> 5, i = idx & 31;
    double inv = exp(-((double)(2 * i) / 64.0) * log(10000.0));
    double a   = (double)s * inv;
    g_sin[idx] = (float)sin(a);
    g_cos[idx] = (float)cos(a);
}

// ---------------------------------------------------------------------------
// RoPE + split to per-head bf16 hi/lo Q/K/V ([b][h][s][d] layout).
// ---------------------------------------------------------------------------
__global__ void __launch_bounds__(256)
rope_split(const float* __restrict__ qkv,
           __nv_bfloat16* __restrict__ Qh, __nv_bfloat16* __restrict__ Ql,
           __nv_bfloat16* __restrict__ Kh, __nv_bfloat16* __restrict__ Kl,
           __nv_bfloat16* __restrict__ Vh, __nv_bfloat16* __restrict__ Vl)
{
    const int token = blockIdx.x;
    const int s = token & (Sn - 1);
    const int b = token >> 10;
    const int t = threadIdx.x;
    const int h = t >> 5;
    const int i = t & 31;
    const float sn = g_sin[s * 32 + i];
    const float cs = g_cos[s * 32 + i];
    const size_t dst = (((size_t)b * Hn + h) * Sn + s) * HDn;

    {
        const float* base = qkv + (size_t)token * (3 * Dn) + h * HDn;
        float x1 = base[i], x2 = base[i + 32];
        split_store(Qh, Ql, dst + i,      x1 * cs - x2 * sn);
        split_store(Qh, Ql, dst + i + 32, x1 * sn + x2 * cs);
    }
    {
        const float* base = qkv + (size_t)token * (3 * Dn) + Dn + h * HDn;
        float x1 = base[i], x2 = base[i + 32];
        split_store(Kh, Kl, dst + i,      x1 * cs - x2 * sn);
        split_store(Kh, Kl, dst + i + 32, x1 * sn + x2 * cs);
    }
    {
        const float* base = qkv + (size_t)token * (3 * Dn) + 2 * Dn + h * HDn;
        split_store(Vh, Vl, dst + i,      base[i]);
        split_store(Vh, Vl, dst + i + 32, base[i + 32]);
    }
}

// ---------------------------------------------------------------------------
// Flash attention, 2-stage cp.async K/V pipeline, 128 q-rows per CTA.
// 256 threads = 8 warps x 16 q-rows. K-tiles of 64.
// Dynamic smem: 2 stages x (Kh|Kl|Vh|Vl, each 64xFPAD); Q staged via stage 0.
// ---------------------------------------------------------------------------
#define FPAD 72
#define FL_STAGE (4 * 64 * FPAD)   // 18432 bf16 elems

__device__ __forceinline__ void fl_load(__nv_bfloat16* base,
    const __nv_bfloat16* Kh, const __nv_bfloat16* Kl,
    const __nv_bfloat16* Vh, const __nv_bfloat16* Vl,
    int t, size_t bh, int k0)
{
    __nv_bfloat16* bKh = base;
    __nv_bfloat16* bKl = bKh + 64 * FPAD;
    __nv_bfloat16* bVh = bKl + 64 * FPAD;
    __nv_bfloat16* bVl = bVh + 64 * FPAD;
#pragma unroll
    for (int u = 0; u < 2; u++) {
        int idx = t + u * 256;              // 512 per array
        int row = idx >> 3, seg = idx & 7;
        size_t go = bh + (size_t)(k0 + row) * HDn + seg * 8;
        cp16(&bKh[row * FPAD + seg * 8], Kh + go);
        cp16(&bKl[row * FPAD + seg * 8], Kl + go);
        cp16(&bVh[row * FPAD + seg * 8], Vh + go);
        cp16(&bVl[row * FPAD + seg * 8], Vl + go);
    }
}

__global__ void __launch_bounds__(256)
flash_attn_mma(const __nv_bfloat16* __restrict__ Qh, const __nv_bfloat16* __restrict__ Ql,
               const __nv_bfloat16* __restrict__ Kh, const __nv_bfloat16* __restrict__ Kl,
               const __nv_bfloat16* __restrict__ Vh, const __nv_bfloat16* __restrict__ Vl,
               __nv_bfloat16* __restrict__ Oh, __nv_bfloat16* __restrict__ Ol)
{
    extern __shared__ __align__(16) __nv_bfloat16 fsm[];

    const int t    = threadIdx.x;
    const int warp = t >> 5, lane = t & 31;
    const int g    = lane >> 2, tig = lane & 3;
    const int l15  = lane & 15, lhi = lane >> 4;
    const int qt   = blockIdx.x, h = blockIdx.y, b = blockIdx.z;
    const int q0   = qt * 128;
    const size_t bh = ((size_t)b * Hn + h) * ((size_t)Sn * HDn);
    const int wr   = warp * 16;            // 0..112

    // ---- stage Q tile (128 rows, hi+lo) into stage-0 buffers ----
    {
        __nv_bfloat16* sQh = fsm;                    // 128 x FPAD
        __nv_bfloat16* sQl = fsm + 128 * FPAD;       // 128 x FPAD
        const __nv_bfloat16* qgh = Qh + bh + (size_t)q0 * HDn;
        const __nv_bfloat16* qgl = Ql + bh + (size_t)q0 * HDn;
#pragma unroll
        for (int u = 0; u < 4; u++) {
            int idx = t + u * 256;                   // 1024 uint4 per array
            int row = idx >> 3, seg = idx & 7;
            *(uint4*)&sQh[row * FPAD + seg * 8] = *(const uint4*)(qgh + row * HDn + seg * 8);
            *(uint4*)&sQl[row * FPAD + seg * 8] = *(const uint4*)(qgl + row * HDn + seg * 8);
        }
    }
    __syncthreads();

    unsigned qa_h[4][4], qa_l[4][4];
#pragma unroll
    for (int kk = 0; kk < 4; kk++) {
        ldsm_x4(qa_h[kk], &fsm[(wr + l15) * FPAD + kk * 16 + lhi * 8]);
        ldsm_x4(qa_l[kk], &fsm[128 * FPAD + (wr + l15) * FPAD + kk * 16 + lhi * 8]);
    }
    __syncthreads();

    float m0 = -INFINITY, m1 = -INFINITY, l0 = 0.f, l1 = 0.f;
    float oacc[8][4];
#pragma unroll
    for (int nt = 0; nt < 8; nt++)
#pragma unroll
        for (int i = 0; i < 4; i++) oacc[nt][i] = 0.f;

    fl_load(fsm, Kh, Kl, Vh, Vl, t, bh, 0);
    CP_COMMIT();

    for (int it = 0; it < Sn / 64; it++) {
        if (it + 1 < Sn / 64) {
            fl_load(fsm + ((it + 1) & 1) * FL_STAGE, Kh, Kl, Vh, Vl,
                    t, bh, (it + 1) * 64);
            CP_COMMIT();
            CP_WAIT(1);
        } else {
            CP_WAIT(0);
        }
        __syncthreads();

        __nv_bfloat16* bKh = fsm + (it & 1) * FL_STAGE;
        __nv_bfloat16* bKl = bKh + 64 * FPAD;
        __nv_bfloat16* bVh = bKl + 64 * FPAD;
        __nv_bfloat16* bVl = bVh + 64 * FPAD;

        // ---- S = Q K^T (3-term split) ----
        float sacc[8][4];
#pragma unroll
        for (int nt = 0; nt < 8; nt++)
#pragma unroll
            for (int i = 0; i < 4; i++) sacc[nt][i] = 0.f;

#pragma unroll
        for (int kk = 0; kk < 4; kk++) {
#pragma unroll
            for (int nt = 0; nt < 8; nt++) {
                unsigned bhf[2], blf[2];
                ldsm_x2(bhf, &bKh[(nt * 8 + (lane & 7)) * FPAD + kk * 16 + ((lane >> 3) & 1) * 8]);
                ldsm_x2(blf, &bKl[(nt * 8 + (lane & 7)) * FPAD + kk * 16 + ((lane >> 3) & 1) * 8]);
                mma16816(sacc[nt], qa_h[kk], bhf);
                mma16816(sacc[nt], qa_h[kk], blf);
                mma16816(sacc[nt], qa_l[kk], bhf);
            }
        }

        // ---- online softmax (rows g, g+8; 4 tig lanes share a row) ----
        float tm0 = -INFINITY, tm1 = -INFINITY;
#pragma unroll
        for (int nt = 0; nt < 8; nt++) {
            sacc[nt][0] *= 0.125f; sacc[nt][1] *= 0.125f;
            sacc[nt][2] *= 0.125f; sacc[nt][3] *= 0.125f;
            tm0 = fmaxf(tm0, fmaxf(sacc[nt][0], sacc[nt][1]));
            tm1 = fmaxf(tm1, fmaxf(sacc[nt][2], sacc[nt][3]));
        }
        tm0 = fmaxf(tm0, __shfl_xor_sync(0xffffffffu, tm0, 1));
        tm0 = fmaxf(tm0, __shfl_xor_sync(0xffffffffu, tm0, 2));
        tm1 = fmaxf(tm1, __shfl_xor_sync(0xffffffffu, tm1, 1));
        tm1 = fmaxf(tm1, __shfl_xor_sync(0xffffffffu, tm1, 2));

        float mn0 = fmaxf(m0, tm0), mn1 = fmaxf(m1, tm1);
        float a0 = __expf(m0 - mn0), a1 = __expf(m1 - mn1);
        m0 = mn0; m1 = mn1;

        float rs0 = 0.f, rs1 = 0.f;
#pragma unroll
        for (int nt = 0; nt < 8; nt++) {
            sacc[nt][0] = __expf(sacc[nt][0] - mn0);
            sacc[nt][1] = __expf(sacc[nt][1] - mn0);
            sacc[nt][2] = __expf(sacc[nt][2] - mn1);
            sacc[nt][3] = __expf(sacc[nt][3] - mn1);
            rs0 += sacc[nt][0] + sacc[nt][1];
            rs1 += sacc[nt][2] + sacc[nt][3];
        }
        rs0 += __shfl_xor_sync(0xffffffffu, rs0, 1);
        rs0 += __shfl_xor_sync(0xffffffffu, rs0, 2);
        rs1 += __shfl_xor_sync(0xffffffffu, rs1, 1);
        rs1 += __shfl_xor_sync(0xffffffffu, rs1, 2);
        l0 = l0 * a0 + rs0;
        l1 = l1 * a1 + rs1;

#pragma unroll
        for (int nt = 0; nt < 8; nt++) {
            oacc[nt][0] *= a0; oacc[nt][1] *= a0;
            oacc[nt][2] *= a1; oacc[nt][3] *= a1;
        }

        // ---- O += P V (P split hi/lo in registers; 3-term) ----
#pragma unroll
        for (int j = 0; j < 4; j++) {
            unsigned pah[4], pal[4];
#pragma unroll
            for (int q = 0; q < 4; q++) {
                int nt = 2 * j + (q >> 1);
                int c0 = (q & 1) * 2;
                float p0 = sacc[nt][c0], p1 = sacc[nt][c0 + 1];
                union { __nv_bfloat162 b2; unsigned u; } hh, ll;
                hh.b2 = __floats2bfloat162_rn(p0, p1);
                float2 hf = __bfloat1622float2(hh.b2);
                ll.b2 = __floats2bfloat162_rn(p0 - hf.x, p1 - hf.y);
                pah[q] = hh.u; pal[q] = ll.u;
            }
#pragma unroll
            for (int nt = 0; nt < 8; nt++) {
                unsigned vbh[2], vbl[2];
                ldsm_x2t(vbh, &bVh[(j * 16 + l15) * FPAD + nt * 8]);
                ldsm_x2t(vbl, &bVl[(j * 16 + l15) * FPAD + nt * 8]);
                mma16816(oacc[nt], pah, vbh);
                mma16816(oacc[nt], pah, vbl);
                mma16816(oacc[nt], pal, vbh);
            }
        }
        __syncthreads();
    }

    // ---- normalize + split-store to (B,S,H*HD) bf16 hi/lo ----
    float inv0 = 1.f / l0, inv1 = 1.f / l1;
    const int gq = q0 + wr + g;
    size_t o0 = (size_t)(b * Sn + gq) * Dn + h * HDn;
    size_t o1 = o0 + (size_t)8 * Dn;
#pragma unroll
    for (int nt = 0; nt < 8; nt++) {
        split2_store(Oh, Ol, o0 + nt * 8 + tig * 2, oacc[nt][0] * inv0, oacc[nt][1] * inv0);
        split2_store(Oh, Ol, o1 + nt * 8 + tig * 2, oacc[nt][2] * inv1, oacc[nt][3] * inv1);
    }
}

// ---------------------------------------------------------------------------
// LayerNorm(X + Y) * g + b, optional bf16 hi/lo split output
// ---------------------------------------------------------------------------
__global__ void __launch_bounds__(256)
ln_residual(const float* __restrict__ X, const float* __restrict__ Y,
            const float* __restrict__ g, const float* __restrict__ bta,
            float* __restrict__ out,
            __nv_bfloat16* __restrict__ outh, __nv_bfloat16* __restrict__ outl)
{
    __shared__ float red[8];
    const int row = blockIdx.x, t = threadIdx.x;
    const float* x = X + (size_t)row * Dn;
    const float* y = Y + (size_t)row * Dn;

    float v0 = x[t] + y[t];
    float v1 = x[t + 256] + y[t + 256];

    const int lane = t & 31, wid = t >> 5;
    float s = v0 + v1;
#pragma unroll
    for (int off = 16; off; off >>= 1) s += __shfl_xor_sync(0xffffffffu, s, off);
    if (!lane) red[wid] = s;
    __syncthreads();
    float mean = 0.f;
#pragma unroll
    for (int i = 0; i < 8; i++) mean += red[i];
    mean *= (1.f / 512.f);
    __syncthreads();

    float d0 = v0 - mean, d1 = v1 - mean;
    float ss = d0 * d0 + d1 * d1;
#pragma unroll
    for (int off = 16; off; off >>= 1) ss += __shfl_xor_sync(0xffffffffu, ss, off);
    if (!lane) red[wid] = ss;
    __syncthreads();
    float var = 0.f;
#pragma unroll
    for (int i = 0; i < 8; i++) var += red[i];
    var *= (1.f / 512.f);
    float inv = rsqrtf(var + 1e-5f);

    float r0 = d0 * inv * g[t]       + bta[t];
    float r1 = d1 * inv * g[t + 256] + bta[t + 256];
    out[(size_t)row * Dn + t]       = r0;
    out[(size_t)row * Dn + t + 256] = r1;
    if (outh) {
        split_store(outh, outl, (size_t)row * Dn + t,       r0);
        split_store(outh, outl, (size_t)row * Dn + t + 256, r1);
    }
}

// ---------------------------------------------------------------------------
// Launch sequence
// ---------------------------------------------------------------------------
static inline void conv(const float* in, __nv_bfloat16* hi, __nv_bfloat16* lo, int n)
{
    convert_split<<<n / 1024, 256>>>(in, hi, lo);
}

extern "C" void kernel_launch(void* const* d_in, const int* in_sizes, int n_in,
                              void* d_out, int out_size)
{
    const float* x      = (const float*)d_in[0];
    const float* w_in   = (const float*)d_in[1];
    const float* b_in   = (const float*)d_in[2];
    const float* w_qkv  = (const float*)d_in[3];
    const float* b_qkv  = (const float*)d_in[4];
    const float* w_out  = (const float*)d_in[5];
    const float* b_out  = (const float*)d_in[6];
    const float* w_ffn1 = (const float*)d_in[7];
    const float* b_ffn1 = (const float*)d_in[8];
    const float* w_ffn2 = (const float*)d_in[9];
    const float* b_ffn2 = (const float*)d_in[10];
    const float* g1     = (const float*)d_in[11];
    const float* bn1    = (const float*)d_in[12];
    const float* g2     = (const float*)d_in[13];
    const float* bn2    = (const float*)d_in[14];
    float* out = (float*)d_out;

    const int BG_SMEM = 2 * BG_STAGE * (int)sizeof(__nv_bfloat16);   // 75776
    const int FL_SMEM = 2 * FL_STAGE * (int)sizeof(__nv_bfloat16);   // 73728
    cudaFuncSetAttribute(bgemm, cudaFuncAttributeMaxDynamicSharedMemorySize, BG_SMEM);
    cudaFuncSetAttribute(flash_attn_mma, cudaFuncAttributeMaxDynamicSharedMemorySize, FL_SMEM);

    float *h, *qkv, *oprj, *h2, *f2;
    cudaGetSymbolAddress((void**)&h,    g_h);
    cudaGetSymbolAddress((void**)&qkv,  g_qkv);
    cudaGetSymbolAddress((void**)&oprj, g_oprj);
    cudaGetSymbolAddress((void**)&h2,   g_h2);
    cudaGetSymbolAddress((void**)&f2,   g_f2);

    __nv_bfloat16 *xh, *xl, *hh, *hl, *ah, *al, *h2h, *h2l, *f1h, *f1l;
    __nv_bfloat16 *w1h, *w1l, *wqh, *wql, *woh, *wol, *wf1h, *wf1l, *wf2h, *wf2l;
    __nv_bfloat16 *qhh, *qhl, *khh, *khl, *vhh, *vhl;
    cudaGetSymbolAddress((void**)&xh,  g_xh);   cudaGetSymbolAddress((void**)&xl,  g_xl);
    cudaGetSymbolAddress((void**)&hh,  g_hh);   cudaGetSymbolAddress((void**)&hl,  g_hl);
    cudaGetSymbolAddress((void**)&ah,  g_ah);   cudaGetSymbolAddress((void**)&al,  g_al);
    cudaGetSymbolAddress((void**)&h2h, g_h2h);  cudaGetSymbolAddress((void**)&h2l, g_h2l);
    cudaGetSymbolAddress((void**)&f1h, g_f1h);  cudaGetSymbolAddress((void**)&f1l, g_f1l);
    cudaGetSymbolAddress((void**)&w1h, g_w1h);  cudaGetSymbolAddress((void**)&w1l, g_w1l);
    cudaGetSymbolAddress((void**)&wqh, g_wqh);  cudaGetSymbolAddress((void**)&wql, g_wql);
    cudaGetSymbolAddress((void**)&woh, g_woh);  cudaGetSymbolAddress((void**)&wol, g_wol);
    cudaGetSymbolAddress((void**)&wf1h, g_wf1h); cudaGetSymbolAddress((void**)&wf1l, g_wf1l);
    cudaGetSymbolAddress((void**)&wf2h, g_wf2h); cudaGetSymbolAddress((void**)&wf2l, g_wf2l);
    cudaGetSymbolAddress((void**)&qhh, g_qheadh); cudaGetSymbolAddress((void**)&qhl, g_qheadl);
    cudaGetSymbolAddress((void**)&khh, g_kheadh); cudaGetSymbolAddress((void**)&khl, g_kheadl);
    cudaGetSymbolAddress((void**)&vhh, g_vheadh); cudaGetSymbolAddress((void**)&vhl, g_vheadl);

    // Split conversions (inputs only; activation splits are fused)
    conv(x,      xh,  xl,  TOK * CIN);
    conv(w_in,   w1h, w1l, CIN * Dn);
    conv(w_qkv,  wqh, wql, Dn * 3 * Dn);
    conv(w_out,  woh, wol, Dn * Dn);
    conv(w_ffn1, wf1h, wf1l, Dn * 4 * Dn);
    conv(w_ffn2, wf2h, wf2l, 4 * Dn * Dn);

    // 1. h = x @ w_in + b_in   (fp32 + split out)
    bgemm<<<dim3(4, 128), 256, BG_SMEM>>>(xh, xl, w1h, w1l, b_in, h, hh, hl, TOK, Dn, CIN, 0);
    // 2. qkv = h @ w_qkv + b_qkv   (fp32 only)
    bgemm<<<dim3(12, 128), 256, BG_SMEM>>>(hh, hl, wqh, wql, b_qkv, qkv,
                                  (__nv_bfloat16*)0, (__nv_bfloat16*)0, TOK, 3 * Dn, Dn, 0);
    // 3. RoPE + per-head split
    rope_table_kernel<<<128, 256>>>();
    rope_split<<<TOK, 256>>>(qkv, qhh, qhl, khh, khl, vhh, vhl);
    // 4. attention (128 q-rows per CTA, split out feeds o-proj directly)
    flash_attn_mma<<<dim3(Sn / 128, Hn, Bn), 256, FL_SMEM>>>(qhh, qhl, khh, khl, vhh, vhl, ah, al);
    // 5. o @ w_out + b_out   (fp32 only)
    bgemm<<<dim3(4, 128), 256, BG_SMEM>>>(ah, al, woh, wol, b_out, oprj,
                                 (__nv_bfloat16*)0, (__nv_bfloat16*)0, TOK, Dn, Dn, 0);
    // 6. h2 = LN(h + o)   (fp32 + split out)
    ln_residual<<<TOK, 256>>>(h, oprj, g1, bn1, h2, h2h, h2l);
    // 7. f1 = relu(h2 @ w_ffn1 + b_ffn1)   (split only)
    bgemm<<<dim3(16, 128), 256, BG_SMEM>>>(h2h, h2l, wf1h, wf1l, b_ffn1, (float*)0,
                                  f1h, f1l, TOK, 4 * Dn, Dn, 1);
    // 8. f2 = f1 @ w_ffn2 + b_ffn2   (fp32 only)
    bgemm<<<dim3(4, 128), 256, BG_SMEM>>>(f1h, f1l, wf2h, wf2l, b_ffn2, f2,
                                 (__nv_bfloat16*)0, (__nv_bfloat16*)0, TOK, Dn, 4 * Dn, 0);
    // 9. out = LN(h2 + f2)
    ln_residual<<<TOK, 256>>>(h2, f2, g2, bn2, out, (__nv_bfloat16*)0, (__nv_bfloat16*)0);
}